// round 1
// baseline (speedup 1.0000x reference)
#include <cuda_runtime.h>
#include <math.h>

#define NH    12
#define HD    128
#define DIM   1536
#define BB    2
#define S_IN  2048
#define S_CTX 256
#define NT    (S_IN + S_CTX)   // 2304
#define Q3    (3 * DIM)        // 4608

// ------------------------- scratch (no cudaMalloc allowed) -------------------
static __device__ float g_qkv_in [(size_t)BB * S_IN  * Q3];   // 75.5 MB
static __device__ float g_qkv_ctx[(size_t)BB * S_CTX * Q3];   //  9.4 MB
static __device__ float g_q[(size_t)BB * NH * NT * HD];       // 28.3 MB
static __device__ float g_k[(size_t)BB * NH * NT * HD];
static __device__ float g_v[(size_t)BB * NH * NT * HD];
static __device__ float g_o[(size_t)BB * NT * DIM];           // 28.3 MB

// ------------------------- fast exp (avoid MUFU bottleneck) ------------------
// exp(x) for x <= 0 (inputs are s - m <= 0). ~2e-5 rel err. 7 FMA + bit trick.
__device__ __forceinline__ float fexp(float x) {
    float t  = fmaxf(x * 1.4426950408889634f, -126.0f);
    float fi = floorf(t);
    float f  = t - fi;
    float p  =               1.5370275e-4f;
    p = fmaf(p, f, 1.3333558e-3f);
    p = fmaf(p, f, 9.6181292e-3f);
    p = fmaf(p, f, 5.5504109e-2f);
    p = fmaf(p, f, 2.4022651e-1f);
    p = fmaf(p, f, 6.9314718e-1f);
    p = fmaf(p, f, 1.0f);
    return p * __int_as_float(((int)fi + 127) << 23);
}

// ------------------------- SGEMM: C = A @ W + bias ---------------------------
// A: [M,K] row-major (lda=K), W: [K,N] row-major, C: [M,N]. M%128==0, N%128==0,
// K%8==0. Batched via grid.z with strides sA/sC (W, bias shared).
__global__ void __launch_bounds__(256, 2)
sgemm_bias_kernel(const float* __restrict__ A, const float* __restrict__ W,
                  const float* __restrict__ bias, float* __restrict__ C,
                  int M, int N, int K, long long sA, long long sC)
{
    __shared__ float As[8][128];
    __shared__ float Bs[8][128];

    const int tid  = threadIdx.x;
    const int tx   = tid & 15;          // 16 col-threads * 8 cols
    const int ty   = tid >> 4;          // 16 row-threads * 8 rows
    const int arow = tid >> 1;          // A tile: 128 rows x 2 float4
    const int acol = (tid & 1) * 4;
    const int brow = tid >> 5;          // B tile: 8 rows x 32 float4
    const int bcol = (tid & 31) * 4;

    const float* Ap = A + blockIdx.z * sA + (long long)blockIdx.y * 128 * K;
    const float* Wp = W + (long long)blockIdx.x * 128;
    const float* bp = bias + (long long)blockIdx.x * 128;
    float*       Cp = C + blockIdx.z * sC + (long long)blockIdx.y * 128 * N
                        + (long long)blockIdx.x * 128;

    float acc[8][8];
    #pragma unroll
    for (int i = 0; i < 8; i++)
        #pragma unroll
        for (int j = 0; j < 8; j++) acc[i][j] = 0.f;

    for (int k0 = 0; k0 < K; k0 += 8) {
        float4 av = *(const float4*)(Ap + (long long)arow * K + k0 + acol);
        float4 bv = *(const float4*)(Wp + (long long)(k0 + brow) * N + bcol);
        As[acol + 0][arow] = av.x;
        As[acol + 1][arow] = av.y;
        As[acol + 2][arow] = av.z;
        As[acol + 3][arow] = av.w;
        *(float4*)&Bs[brow][bcol] = bv;
        __syncthreads();

        #pragma unroll
        for (int k = 0; k < 8; k++) {
            float ra[8], rb[8];
            float4 a0 = *(const float4*)&As[k][ty * 8];
            float4 a1 = *(const float4*)&As[k][ty * 8 + 4];
            float4 b0 = *(const float4*)&Bs[k][tx * 8];
            float4 b1 = *(const float4*)&Bs[k][tx * 8 + 4];
            ra[0]=a0.x; ra[1]=a0.y; ra[2]=a0.z; ra[3]=a0.w;
            ra[4]=a1.x; ra[5]=a1.y; ra[6]=a1.z; ra[7]=a1.w;
            rb[0]=b0.x; rb[1]=b0.y; rb[2]=b0.z; rb[3]=b0.w;
            rb[4]=b1.x; rb[5]=b1.y; rb[6]=b1.z; rb[7]=b1.w;
            #pragma unroll
            for (int i = 0; i < 8; i++)
                #pragma unroll
                for (int j = 0; j < 8; j++)
                    acc[i][j] = fmaf(ra[i], rb[j], acc[i][j]);
        }
        __syncthreads();
    }

    #pragma unroll
    for (int i = 0; i < 8; i++) {
        long long row = (long long)(ty * 8 + i) * N;
        #pragma unroll
        for (int j = 0; j < 8; j += 4) {
            int col = tx * 8 + j;
            float4 o;
            o.x = acc[i][j + 0] + bp[col + 0];
            o.y = acc[i][j + 1] + bp[col + 1];
            o.z = acc[i][j + 2] + bp[col + 2];
            o.w = acc[i][j + 3] + bp[col + 3];
            *(float4*)(Cp + row + col) = o;
        }
    }
}

// ----------------- RMSNorm + RoPE + scatter to [b][h][n][d] ------------------
__global__ void __launch_bounds__(256)
normrope_kernel(const float* __restrict__ qs_in, const float* __restrict__ ks_in,
                const float* __restrict__ qs_ctx, const float* __restrict__ ks_ctx)
{
    const int pos = blockIdx.x;     // 0..NT-1 (concat order: ctx first)
    const int b   = blockIdx.y;
    const int t   = threadIdx.x;

    __shared__ float buf[DIM];
    __shared__ float red[8];
    __shared__ float cosv[64], sinv[64];

    const float* src; const float* qs; const float* ks;
    if (pos < S_CTX) {
        src = g_qkv_ctx + ((long long)b * S_CTX + pos) * Q3;
        qs = qs_ctx; ks = ks_ctx;
    } else {
        src = g_qkv_in + ((long long)b * S_IN + (pos - S_CTX)) * Q3;
        qs = qs_in; ks = ks_in;
    }

    if (t < 64) {
        double ang = (double)pos * pow(10000.0, -(double)t / 64.0);
        cosv[t] = (float)cos(ang);
        sinv[t] = (float)sin(ang);
    }

    #pragma unroll
    for (int which = 0; which < 2; which++) {
        const float* x  = src + which * DIM;
        const float* sc = which ? ks : qs;
        float v[6];
        float local = 0.f;
        #pragma unroll
        for (int i = 0; i < 6; i++) {
            v[i] = x[t + i * 256];
            local = fmaf(v[i], v[i], local);
        }
        #pragma unroll
        for (int off = 16; off; off >>= 1)
            local += __shfl_xor_sync(0xffffffffu, local, off);
        if ((t & 31) == 0) red[t >> 5] = local;
        __syncthreads();
        float tot = red[0] + red[1] + red[2] + red[3]
                  + red[4] + red[5] + red[6] + red[7];
        float r = rsqrtf(tot * (1.0f / DIM) + 1e-6f);
        #pragma unroll
        for (int i = 0; i < 6; i++)
            buf[t + i * 256] = v[i] * r * sc[t + i * 256];
        __syncthreads();

        float* dst = which ? g_k : g_q;
        #pragma unroll
        for (int i = 0; i < 6; i++) {
            int e = t + i * 256;
            int hh = e >> 7, d = e & 127, j = d & 63;
            float c = cosv[j], sn = sinv[j];
            float y = (d < 64) ? (buf[e] * c - buf[e + 64] * sn)
                               : (buf[e] * c + buf[e - 64] * sn);
            dst[(((long long)b * NH + hh) * NT + pos) * HD + d] = y;
        }
        __syncthreads();
    }

    // V: straight copy (no norm / rope)
    #pragma unroll
    for (int i = 0; i < 6; i++) {
        int e = t + i * 256;
        int hh = e >> 7, d = e & 127;
        g_v[(((long long)b * NH + hh) * NT + pos) * HD + d] = src[2 * DIM + e];
    }
}

// ------------------------- flash attention -----------------------------------
// Block = (q-tile of 128, head, batch). 256 threads. K/V tiles of 64.
// Smem: Qst[d][q] 128x128, Kst[d][kk] 128x64 (both d-major -> conflict-free
// reads in the score loop), Vs[kk][d] 64x128, Ps[q][kk] 128x65 (padded).
#define SM_ATTN ((128*128 + 128*64 + 64*128 + 128*65) * 4)

__global__ void __launch_bounds__(256, 1)
attn_kernel(void)
{
    extern __shared__ float sm[];
    float* Qst = sm;                 // [128][128] d-major, pre-scaled
    float* Kst = Qst + 128 * 128;    // [128][64]  d-major
    float* Vs  = Kst + 128 * 64;     // [64][128]
    float* Ps  = Vs  + 64 * 128;     // [128][65]

    const int qt = blockIdx.x, h = blockIdx.y, b = blockIdx.z;
    const long long base = (((long long)b * NH + h) * NT) * HD;
    const float* Qg = g_q + base + (long long)qt * 128 * HD;
    const float* Kg = g_k + base;
    const float* Vg = g_v + base;

    const int tid = threadIdx.x;
    const int ty  = tid >> 3;   // 0..31 : 4 queries each (q = ty*4+i)
    const int tx  = tid & 7;    // keys: tx+8j ; d-cols: 32g + 4tx + c

    const float scale = 0.088388347648318447f;  // 128^-0.5

    // Load Q tile, transposed + pre-scaled
    #pragma unroll
    for (int it = 0; it < 16; it++) {
        int idx = tid + it * 256;        // 0..4095
        int q   = idx & 127;
        int d4  = idx >> 7;              // 0..31
        float4 v = *(const float4*)(Qg + (long long)q * HD + d4 * 4);
        Qst[(d4 * 4 + 0) * 128 + q] = v.x * scale;
        Qst[(d4 * 4 + 1) * 128 + q] = v.y * scale;
        Qst[(d4 * 4 + 2) * 128 + q] = v.z * scale;
        Qst[(d4 * 4 + 3) * 128 + q] = v.w * scale;
    }

    float O[4][16];
    #pragma unroll
    for (int i = 0; i < 4; i++)
        #pragma unroll
        for (int c = 0; c < 16; c++) O[i][c] = 0.f;
    float m[4] = {-1e30f, -1e30f, -1e30f, -1e30f};
    float l[4] = {0.f, 0.f, 0.f, 0.f};

    __syncthreads();

    for (int kt = 0; kt < NT / 64; kt++) {
        // Load K tile (transposed) + V tile
        #pragma unroll
        for (int it = 0; it < 8; it++) {
            int idx = tid + it * 256;    // 0..2047
            {
                int kk = idx & 63;
                int d4 = idx >> 6;       // 0..31
                float4 v = *(const float4*)(Kg + (long long)(kt * 64 + kk) * HD + d4 * 4);
                Kst[(d4 * 4 + 0) * 64 + kk] = v.x;
                Kst[(d4 * 4 + 1) * 64 + kk] = v.y;
                Kst[(d4 * 4 + 2) * 64 + kk] = v.z;
                Kst[(d4 * 4 + 3) * 64 + kk] = v.w;
            }
            {
                int kk = idx >> 5;
                int d4 = idx & 31;
                *(float4*)(Vs + kk * 128 + d4 * 4) =
                    *(const float4*)(Vg + (long long)(kt * 64 + kk) * HD + d4 * 4);
            }
        }
        __syncthreads();

        // S = Qs @ Ks^T  (already scaled)
        float s[4][8];
        #pragma unroll
        for (int i = 0; i < 4; i++)
            #pragma unroll
            for (int j = 0; j < 8; j++) s[i][j] = 0.f;

        #pragma unroll 4
        for (int d = 0; d < 128; d++) {
            float rq[4], rk[8];
            float4 qv = *(const float4*)&Qst[d * 128 + ty * 4];
            rq[0] = qv.x; rq[1] = qv.y; rq[2] = qv.z; rq[3] = qv.w;
            #pragma unroll
            for (int j = 0; j < 8; j++) rk[j] = Kst[d * 64 + tx + 8 * j];
            #pragma unroll
            for (int i = 0; i < 4; i++)
                #pragma unroll
                for (int j = 0; j < 8; j++)
                    s[i][j] = fmaf(rq[i], rk[j], s[i][j]);
        }

        // Online softmax (8-lane groups share a query row)
        #pragma unroll
        for (int i = 0; i < 4; i++) {
            float mx = s[i][0];
            #pragma unroll
            for (int j = 1; j < 8; j++) mx = fmaxf(mx, s[i][j]);
            mx = fmaxf(mx, __shfl_xor_sync(0xffffffffu, mx, 1));
            mx = fmaxf(mx, __shfl_xor_sync(0xffffffffu, mx, 2));
            mx = fmaxf(mx, __shfl_xor_sync(0xffffffffu, mx, 4));
            float mn = fmaxf(m[i], mx);
            float al = fexp(m[i] - mn);
            float ls = 0.f;
            #pragma unroll
            for (int j = 0; j < 8; j++) {
                float p = fexp(s[i][j] - mn);
                s[i][j] = p;
                ls += p;
            }
            ls += __shfl_xor_sync(0xffffffffu, ls, 1);
            ls += __shfl_xor_sync(0xffffffffu, ls, 2);
            ls += __shfl_xor_sync(0xffffffffu, ls, 4);
            l[i] = l[i] * al + ls;
            m[i] = mn;
            #pragma unroll
            for (int c = 0; c < 16; c++) O[i][c] *= al;
            #pragma unroll
            for (int j = 0; j < 8; j++)
                Ps[(ty * 4 + i) * 65 + tx + 8 * j] = s[i][j];
        }
        __syncthreads();

        // O += P @ V
        #pragma unroll 4
        for (int kk = 0; kk < 64; kk++) {
            float p0 = Ps[(ty * 4 + 0) * 65 + kk];
            float p1 = Ps[(ty * 4 + 1) * 65 + kk];
            float p2 = Ps[(ty * 4 + 2) * 65 + kk];
            float p3 = Ps[(ty * 4 + 3) * 65 + kk];
            #pragma unroll
            for (int g = 0; g < 4; g++) {
                float4 v = *(const float4*)(Vs + kk * 128 + g * 32 + tx * 4);
                float vv[4] = {v.x, v.y, v.z, v.w};
                #pragma unroll
                for (int c = 0; c < 4; c++) {
                    O[0][g * 4 + c] = fmaf(p0, vv[c], O[0][g * 4 + c]);
                    O[1][g * 4 + c] = fmaf(p1, vv[c], O[1][g * 4 + c]);
                    O[2][g * 4 + c] = fmaf(p2, vv[c], O[2][g * 4 + c]);
                    O[3][g * 4 + c] = fmaf(p3, vv[c], O[3][g * 4 + c]);
                }
            }
        }
        __syncthreads();
    }

    // Epilogue: normalize, write to g_o[b][pos][h*128 + d]
    #pragma unroll
    for (int i = 0; i < 4; i++) {
        float inv = 1.0f / l[i];
        long long q = (long long)qt * 128 + ty * 4 + i;
        float* op = g_o + ((long long)b * NT + q) * DIM + h * HD;
        #pragma unroll
        for (int g = 0; g < 4; g++) {
            float4 o;
            o.x = O[i][g * 4 + 0] * inv;
            o.y = O[i][g * 4 + 1] * inv;
            o.z = O[i][g * 4 + 2] * inv;
            o.w = O[i][g * 4 + 3] * inv;
            *(float4*)(op + g * 32 + tx * 4) = o;
        }
    }
}

// ------------------------- launch --------------------------------------------
extern "C" void kernel_launch(void* const* d_in, const int* in_sizes, int n_in,
                              void* d_out, int out_size)
{
    (void)in_sizes; (void)n_in; (void)out_size;

    const float* input     = (const float*)d_in[0];
    const float* context   = (const float*)d_in[1];
    const float* W_qkv_in  = (const float*)d_in[2];
    const float* b_qkv_in  = (const float*)d_in[3];
    const float* W_qkv_ctx = (const float*)d_in[4];
    const float* b_qkv_ctx = (const float*)d_in[5];
    const float* qs_in     = (const float*)d_in[6];
    const float* ks_in     = (const float*)d_in[7];
    const float* qs_ctx    = (const float*)d_in[8];
    const float* ks_ctx    = (const float*)d_in[9];
    const float* W_out_in  = (const float*)d_in[10];
    const float* b_out_in  = (const float*)d_in[11];
    const float* W_out_ctx = (const float*)d_in[12];
    const float* b_out_ctx = (const float*)d_in[13];
    float* out = (float*)d_out;

    float *qkv_in, *qkv_ctx, *o;
    cudaGetSymbolAddress((void**)&qkv_in,  g_qkv_in);
    cudaGetSymbolAddress((void**)&qkv_ctx, g_qkv_ctx);
    cudaGetSymbolAddress((void**)&o,       g_o);

    // 1) QKV projections
    sgemm_bias_kernel<<<dim3(Q3 / 128, (BB * S_IN) / 128, 1), 256>>>(
        input, W_qkv_in, b_qkv_in, qkv_in, BB * S_IN, Q3, DIM, 0, 0);
    sgemm_bias_kernel<<<dim3(Q3 / 128, (BB * S_CTX) / 128, 1), 256>>>(
        context, W_qkv_ctx, b_qkv_ctx, qkv_ctx, BB * S_CTX, Q3, DIM, 0, 0);

    // 2) RMSNorm + RoPE + scatter
    normrope_kernel<<<dim3(NT, BB), 256>>>(qs_in, ks_in, qs_ctx, ks_ctx);

    // 3) Attention
    cudaFuncSetAttribute(attn_kernel,
                         cudaFuncAttributeMaxDynamicSharedMemorySize, SM_ATTN);
    attn_kernel<<<dim3(NT / 128, NH, BB), 256, SM_ATTN>>>();

    // 4) Output projections (input part first, then context part)
    sgemm_bias_kernel<<<dim3(DIM / 128, S_IN / 128, BB), 256>>>(
        o + (long long)S_CTX * DIM, W_out_in, b_out_in, out,
        S_IN, DIM, DIM, (long long)NT * DIM, (long long)S_IN * DIM);
    sgemm_bias_kernel<<<dim3(DIM / 128, S_CTX / 128, BB), 256>>>(
        o, W_out_ctx, b_out_ctx, out + (long long)BB * S_IN * DIM,
        S_CTX, DIM, DIM, (long long)NT * DIM, (long long)S_CTX * DIM);
}

// round 2
// speedup vs baseline: 3.0795x; 3.0795x over previous
#include <cuda_runtime.h>
#include <math.h>

#define NH    12
#define HD    128
#define DIM   1536
#define BB    2
#define S_IN  2048
#define S_CTX 256
#define NT    (S_IN + S_CTX)   // 2304
#define Q3    (3 * DIM)        // 4608

// ------------------------- scratch (no cudaMalloc allowed) -------------------
static __device__ float g_qkv_in [(size_t)BB * S_IN  * Q3];
static __device__ float g_qkv_ctx[(size_t)BB * S_CTX * Q3];
static __device__ float g_q[(size_t)BB * NH * NT * HD];
static __device__ float g_k[(size_t)BB * NH * NT * HD];
static __device__ float g_v[(size_t)BB * NH * NT * HD];
static __device__ float g_o[(size_t)BB * NT * DIM];

// ------------------------- helpers -------------------------------------------
__device__ __forceinline__ float to_tf32(float x) {
    float r;
    asm("cvt.rna.tf32.f32 %0, %1;" : "=f"(r) : "f"(x));
    return r;
}

__device__ __forceinline__ void mma8(float* c, const unsigned* a,
                                     unsigned b0, unsigned b1) {
    asm volatile(
        "mma.sync.aligned.m16n8k8.row.col.f32.tf32.tf32.f32 "
        "{%0,%1,%2,%3}, {%4,%5,%6,%7}, {%8,%9}, {%0,%1,%2,%3};"
        : "+f"(c[0]), "+f"(c[1]), "+f"(c[2]), "+f"(c[3])
        : "r"(a[0]), "r"(a[1]), "r"(a[2]), "r"(a[3]), "r"(b0), "r"(b1));
}

// fast exp for x <= 0 (softmax). ~2e-5 rel err.
__device__ __forceinline__ float fexp(float x) {
    float t  = fmaxf(x * 1.4426950408889634f, -126.0f);
    float fi = floorf(t);
    float f  = t - fi;
    float p  =               1.5370275e-4f;
    p = fmaf(p, f, 1.3333558e-3f);
    p = fmaf(p, f, 9.6181292e-3f);
    p = fmaf(p, f, 5.5504109e-2f);
    p = fmaf(p, f, 2.4022651e-1f);
    p = fmaf(p, f, 6.9314718e-1f);
    p = fmaf(p, f, 1.0f);
    return p * __int_as_float(((int)fi + 127) << 23);
}

// ------------------------- TF32 GEMM: C = A @ W + bias -----------------------
// A:[M,K] rm, W:[K,N] rm, C:[M,N]. M%128==0, N%128==0, K%32==0.
// Block 128x128, k-chunk 32. 256 thr, 8 warps (2x4), warp tile 64x32.
// As stride 36, Bs stride 136 -> all fragment LDS are bank-conflict-free.
__global__ void __launch_bounds__(256)
gemm_tf32(const float* __restrict__ A, const float* __restrict__ W,
          const float* __restrict__ bias, float* __restrict__ C,
          int M, int N, int K, long long sA, long long sC)
{
    __shared__ float As[128][36];
    __shared__ float Bs[32][136];

    const int tid  = threadIdx.x;
    const int lane = tid & 31;
    const int wid  = tid >> 5;
    const int wm   = (wid & 1) * 64;
    const int wn   = (wid >> 1) * 32;
    const int l4   = lane >> 2;     // 0..7
    const int lm   = lane & 3;      // 0..3

    const float* Ap = A + blockIdx.z * sA + (long long)blockIdx.y * 128 * K;
    const float* Wp = W + (long long)blockIdx.x * 128;
    const float* bp = bias + (long long)blockIdx.x * 128;
    float*       Cp = C + blockIdx.z * sC + (long long)blockIdx.y * 128 * N
                        + (long long)blockIdx.x * 128;

    const int ar = tid >> 3;            // A rows ar+32i, i=0..3
    const int ac = (tid & 7) * 4;
    const int br = tid >> 5;            // B rows br+8i, i=0..3
    const int bc = (tid & 31) * 4;

    float4 pa[4], pb[4];
    #pragma unroll
    for (int i = 0; i < 4; i++)
        pa[i] = *(const float4*)(Ap + (long long)(ar + 32 * i) * K + ac);
    #pragma unroll
    for (int i = 0; i < 4; i++)
        pb[i] = *(const float4*)(Wp + (long long)(br + 8 * i) * N + bc);

    float acc[4][4][4];
    #pragma unroll
    for (int mi = 0; mi < 4; mi++)
        #pragma unroll
        for (int ni = 0; ni < 4; ni++)
            #pragma unroll
            for (int c = 0; c < 4; c++) acc[mi][ni][c] = 0.f;

    for (int k0 = 0; k0 < K; k0 += 32) {
        #pragma unroll
        for (int i = 0; i < 4; i++) {
            float4 v = pa[i];
            v.x = to_tf32(v.x); v.y = to_tf32(v.y);
            v.z = to_tf32(v.z); v.w = to_tf32(v.w);
            *(float4*)&As[ar + 32 * i][ac] = v;
        }
        #pragma unroll
        for (int i = 0; i < 4; i++) {
            float4 v = pb[i];
            v.x = to_tf32(v.x); v.y = to_tf32(v.y);
            v.z = to_tf32(v.z); v.w = to_tf32(v.w);
            *(float4*)&Bs[br + 8 * i][bc] = v;
        }
        __syncthreads();

        if (k0 + 32 < K) {
            #pragma unroll
            for (int i = 0; i < 4; i++)
                pa[i] = *(const float4*)(Ap + (long long)(ar + 32 * i) * K
                                         + k0 + 32 + ac);
            #pragma unroll
            for (int i = 0; i < 4; i++)
                pb[i] = *(const float4*)(Wp + (long long)(k0 + 32 + br + 8 * i) * N
                                         + bc);
        }

        #pragma unroll
        for (int ks = 0; ks < 4; ks++) {
            unsigned a[4][4];
            #pragma unroll
            for (int mi = 0; mi < 4; mi++) {
                int r = wm + mi * 16 + l4;
                int c = ks * 8 + lm;
                a[mi][0] = __float_as_uint(As[r][c]);
                a[mi][1] = __float_as_uint(As[r + 8][c]);
                a[mi][2] = __float_as_uint(As[r][c + 4]);
                a[mi][3] = __float_as_uint(As[r + 8][c + 4]);
            }
            #pragma unroll
            for (int ni = 0; ni < 4; ni++) {
                int cc = wn + ni * 8 + l4;
                int rr = ks * 8 + lm;
                unsigned b0 = __float_as_uint(Bs[rr][cc]);
                unsigned b1 = __float_as_uint(Bs[rr + 4][cc]);
                #pragma unroll
                for (int mi = 0; mi < 4; mi++)
                    mma8(acc[mi][ni], a[mi], b0, b1);
            }
        }
        __syncthreads();
    }

    #pragma unroll
    for (int mi = 0; mi < 4; mi++) {
        #pragma unroll
        for (int ni = 0; ni < 4; ni++) {
            int r0 = wm + mi * 16 + l4;
            int c0 = wn + ni * 8 + lm * 2;
            float bx = bp[c0], by = bp[c0 + 1];
            float2 o0 = make_float2(acc[mi][ni][0] + bx, acc[mi][ni][1] + by);
            float2 o1 = make_float2(acc[mi][ni][2] + bx, acc[mi][ni][3] + by);
            *(float2*)(Cp + (long long)r0 * N + c0)       = o0;
            *(float2*)(Cp + (long long)(r0 + 8) * N + c0) = o1;
        }
    }
}

// ----------------- RMSNorm + RoPE + scatter to [b][h][n][d] ------------------
__global__ void __launch_bounds__(256)
normrope_kernel(const float* __restrict__ qs_in, const float* __restrict__ ks_in,
                const float* __restrict__ qs_ctx, const float* __restrict__ ks_ctx)
{
    const int pos = blockIdx.x;
    const int b   = blockIdx.y;
    const int t   = threadIdx.x;

    __shared__ float buf[DIM];
    __shared__ float red[8];
    __shared__ float cosv[64], sinv[64];

    const float* src; const float* qs; const float* ks;
    if (pos < S_CTX) {
        src = g_qkv_ctx + ((long long)b * S_CTX + pos) * Q3;
        qs = qs_ctx; ks = ks_ctx;
    } else {
        src = g_qkv_in + ((long long)b * S_IN + (pos - S_CTX)) * Q3;
        qs = qs_in; ks = ks_in;
    }

    if (t < 64) {
        double ang = (double)pos * pow(10000.0, -(double)t / 64.0);
        cosv[t] = (float)cos(ang);
        sinv[t] = (float)sin(ang);
    }

    #pragma unroll
    for (int which = 0; which < 2; which++) {
        const float* x  = src + which * DIM;
        const float* sc = which ? ks : qs;
        float v[6];
        float local = 0.f;
        #pragma unroll
        for (int i = 0; i < 6; i++) {
            v[i] = x[t + i * 256];
            local = fmaf(v[i], v[i], local);
        }
        #pragma unroll
        for (int off = 16; off; off >>= 1)
            local += __shfl_xor_sync(0xffffffffu, local, off);
        if ((t & 31) == 0) red[t >> 5] = local;
        __syncthreads();
        float tot = red[0] + red[1] + red[2] + red[3]
                  + red[4] + red[5] + red[6] + red[7];
        float r = rsqrtf(tot * (1.0f / DIM) + 1e-6f);
        #pragma unroll
        for (int i = 0; i < 6; i++)
            buf[t + i * 256] = v[i] * r * sc[t + i * 256];
        __syncthreads();

        float* dst = which ? g_k : g_q;
        #pragma unroll
        for (int i = 0; i < 6; i++) {
            int e = t + i * 256;
            int hh = e >> 7, d = e & 127, j = d & 63;
            float c = cosv[j], sn = sinv[j];
            float y = (d < 64) ? (buf[e] * c - buf[e + 64] * sn)
                               : (buf[e] * c + buf[e - 64] * sn);
            dst[(((long long)b * NH + hh) * NT + pos) * HD + d] = y;
        }
        __syncthreads();
    }

    #pragma unroll
    for (int i = 0; i < 6; i++) {
        int e = t + i * 256;
        int hh = e >> 7, d = e & 127;
        g_v[(((long long)b * NH + hh) * NT + pos) * HD + d] = src[2 * DIM + e];
    }
}

// ------------------------- TF32 flash attention ------------------------------
// Block = (128-query tile, head, batch). 256 thr, 8 warps, each warp owns 16 q.
// Smem strides chosen so every MMA fragment LDS hits 32 distinct banks.
#define QS_STR 132
#define KS_STR 132
#define VS_STR 136
#define PS_STR 68
#define SM_ATTN ((128*QS_STR + 64*KS_STR + 64*VS_STR + 128*PS_STR) * 4)

__global__ void __launch_bounds__(256, 1)
attn_kernel(void)
{
    extern __shared__ float sm[];
    float* Qs = sm;                       // [128][132]
    float* Ks = Qs + 128 * QS_STR;        // [64][132]
    float* Vs = Ks + 64  * KS_STR;        // [64][136]
    float* Ps = Vs + 64  * VS_STR;        // [128][68]

    const int qt = blockIdx.x, h = blockIdx.y, b = blockIdx.z;
    const long long base = (((long long)b * NH + h) * NT) * HD;
    const float* Qg = g_q + base + (long long)qt * 128 * HD;
    const float* Kg = g_k + base;
    const float* Vg = g_v + base;

    const int tid  = threadIdx.x;
    const int lane = tid & 31;
    const int wid  = tid >> 5;
    const int l4   = lane >> 2;   // 0..7
    const int lm   = lane & 3;    // 0..3
    const int q0   = wid * 16;    // warp's query row block

    const float scale = 0.088388347648318447f;  // 128^-0.5

    // Load + scale + tf32-round Q tile
    #pragma unroll
    for (int it = 0; it < 16; it++) {
        int lin = tid + it * 256;         // 0..4095
        int q   = lin >> 5;
        int c4  = (lin & 31) * 4;
        float4 v = *(const float4*)(Qg + (long long)q * HD + c4);
        v.x = to_tf32(v.x * scale); v.y = to_tf32(v.y * scale);
        v.z = to_tf32(v.z * scale); v.w = to_tf32(v.w * scale);
        *(float4*)&Qs[q * QS_STR + c4] = v;
    }

    float O[16][4];
    #pragma unroll
    for (int ni = 0; ni < 16; ni++)
        #pragma unroll
        for (int c = 0; c < 4; c++) O[ni][c] = 0.f;
    float m0 = -1e30f, m1 = -1e30f, l0 = 0.f, l1 = 0.f;

    for (int kt = 0; kt < NT / 64; kt++) {
        __syncthreads();   // Vs/Ks free to overwrite
        #pragma unroll
        for (int it = 0; it < 8; it++) {
            int lin = tid + it * 256;     // 0..2047
            int r   = lin >> 5;
            int c4  = (lin & 31) * 4;
            const float* kg = Kg + (long long)(kt * 64 + r) * HD + c4;
            float4 v = *(const float4*)kg;
            v.x = to_tf32(v.x); v.y = to_tf32(v.y);
            v.z = to_tf32(v.z); v.w = to_tf32(v.w);
            *(float4*)&Ks[r * KS_STR + c4] = v;
            const float* vg = Vg + (long long)(kt * 64 + r) * HD + c4;
            float4 w = *(const float4*)vg;
            w.x = to_tf32(w.x); w.y = to_tf32(w.y);
            w.z = to_tf32(w.z); w.w = to_tf32(w.w);
            *(float4*)&Vs[r * VS_STR + c4] = w;
        }
        __syncthreads();

        // S = Q @ K^T : warp computes rows q0..q0+15 x 64 keys
        float s[8][4];
        #pragma unroll
        for (int ni = 0; ni < 8; ni++)
            #pragma unroll
            for (int c = 0; c < 4; c++) s[ni][c] = 0.f;

        #pragma unroll
        for (int ks = 0; ks < 16; ks++) {
            unsigned a[4];
            int r = q0 + l4;
            int c = ks * 8 + lm;
            a[0] = __float_as_uint(Qs[r * QS_STR + c]);
            a[1] = __float_as_uint(Qs[(r + 8) * QS_STR + c]);
            a[2] = __float_as_uint(Qs[r * QS_STR + c + 4]);
            a[3] = __float_as_uint(Qs[(r + 8) * QS_STR + c + 4]);
            #pragma unroll
            for (int ni = 0; ni < 8; ni++) {
                int key = ni * 8 + l4;
                unsigned b0 = __float_as_uint(Ks[key * KS_STR + ks * 8 + lm]);
                unsigned b1 = __float_as_uint(Ks[key * KS_STR + ks * 8 + lm + 4]);
                mma8(s[ni], a, b0, b1);
            }
        }

        // online softmax: thread holds rows (q0+l4, q0+l4+8), cols ni*8+lm*2+{0,1}
        float mx0 = -1e30f, mx1 = -1e30f;
        #pragma unroll
        for (int ni = 0; ni < 8; ni++) {
            mx0 = fmaxf(mx0, fmaxf(s[ni][0], s[ni][1]));
            mx1 = fmaxf(mx1, fmaxf(s[ni][2], s[ni][3]));
        }
        mx0 = fmaxf(mx0, __shfl_xor_sync(0xffffffffu, mx0, 1));
        mx0 = fmaxf(mx0, __shfl_xor_sync(0xffffffffu, mx0, 2));
        mx1 = fmaxf(mx1, __shfl_xor_sync(0xffffffffu, mx1, 1));
        mx1 = fmaxf(mx1, __shfl_xor_sync(0xffffffffu, mx1, 2));

        float mn0 = fmaxf(m0, mx0), mn1 = fmaxf(m1, mx1);
        float al0 = fexp(m0 - mn0), al1 = fexp(m1 - mn1);
        float ls0 = 0.f, ls1 = 0.f;
        #pragma unroll
        for (int ni = 0; ni < 8; ni++) {
            float p0 = fexp(s[ni][0] - mn0);
            float p1 = fexp(s[ni][1] - mn0);
            float p2 = fexp(s[ni][2] - mn1);
            float p3 = fexp(s[ni][3] - mn1);
            ls0 += p0 + p1; ls1 += p2 + p3;
            int cc = ni * 8 + lm * 2;
            *(float2*)&Ps[(q0 + l4) * PS_STR + cc]     =
                make_float2(to_tf32(p0), to_tf32(p1));
            *(float2*)&Ps[(q0 + l4 + 8) * PS_STR + cc] =
                make_float2(to_tf32(p2), to_tf32(p3));
        }
        ls0 += __shfl_xor_sync(0xffffffffu, ls0, 1);
        ls0 += __shfl_xor_sync(0xffffffffu, ls0, 2);
        ls1 += __shfl_xor_sync(0xffffffffu, ls1, 1);
        ls1 += __shfl_xor_sync(0xffffffffu, ls1, 2);
        l0 = l0 * al0 + ls0;  m0 = mn0;
        l1 = l1 * al1 + ls1;  m1 = mn1;
        #pragma unroll
        for (int ni = 0; ni < 16; ni++) {
            O[ni][0] *= al0; O[ni][1] *= al0;
            O[ni][2] *= al1; O[ni][3] *= al1;
        }
        __syncwarp();

        // O += P @ V  (warp-private rows of Ps)
        #pragma unroll
        for (int ks = 0; ks < 8; ks++) {
            unsigned a[4];
            int r = q0 + l4;
            int c = ks * 8 + lm;
            a[0] = __float_as_uint(Ps[r * PS_STR + c]);
            a[1] = __float_as_uint(Ps[(r + 8) * PS_STR + c]);
            a[2] = __float_as_uint(Ps[r * PS_STR + c + 4]);
            a[3] = __float_as_uint(Ps[(r + 8) * PS_STR + c + 4]);
            #pragma unroll
            for (int ni = 0; ni < 16; ni++) {
                int kk = ks * 8 + lm;
                int dd = ni * 8 + l4;
                unsigned b0 = __float_as_uint(Vs[kk * VS_STR + dd]);
                unsigned b1 = __float_as_uint(Vs[(kk + 4) * VS_STR + dd]);
                mma8(O[ni], a, b0, b1);
            }
        }
    }

    // epilogue
    float inv0 = 1.0f / l0, inv1 = 1.0f / l1;
    long long r0 = (long long)qt * 128 + q0 + l4;
    float* op0 = g_o + ((long long)b * NT + r0) * DIM + h * HD;
    float* op1 = g_o + ((long long)b * NT + r0 + 8) * DIM + h * HD;
    #pragma unroll
    for (int ni = 0; ni < 16; ni++) {
        int cc = ni * 8 + lm * 2;
        *(float2*)(op0 + cc) = make_float2(O[ni][0] * inv0, O[ni][1] * inv0);
        *(float2*)(op1 + cc) = make_float2(O[ni][2] * inv1, O[ni][3] * inv1);
    }
}

// ------------------------- launch --------------------------------------------
extern "C" void kernel_launch(void* const* d_in, const int* in_sizes, int n_in,
                              void* d_out, int out_size)
{
    (void)in_sizes; (void)n_in; (void)out_size;

    const float* input     = (const float*)d_in[0];
    const float* context   = (const float*)d_in[1];
    const float* W_qkv_in  = (const float*)d_in[2];
    const float* b_qkv_in  = (const float*)d_in[3];
    const float* W_qkv_ctx = (const float*)d_in[4];
    const float* b_qkv_ctx = (const float*)d_in[5];
    const float* qs_in     = (const float*)d_in[6];
    const float* ks_in     = (const float*)d_in[7];
    const float* qs_ctx    = (const float*)d_in[8];
    const float* ks_ctx    = (const float*)d_in[9];
    const float* W_out_in  = (const float*)d_in[10];
    const float* b_out_in  = (const float*)d_in[11];
    const float* W_out_ctx = (const float*)d_in[12];
    const float* b_out_ctx = (const float*)d_in[13];
    float* out = (float*)d_out;

    float *qkv_in, *qkv_ctx, *o;
    cudaGetSymbolAddress((void**)&qkv_in,  g_qkv_in);
    cudaGetSymbolAddress((void**)&qkv_ctx, g_qkv_ctx);
    cudaGetSymbolAddress((void**)&o,       g_o);

    // 1) QKV projections
    gemm_tf32<<<dim3(Q3 / 128, (BB * S_IN) / 128, 1), 256>>>(
        input, W_qkv_in, b_qkv_in, qkv_in, BB * S_IN, Q3, DIM, 0, 0);
    gemm_tf32<<<dim3(Q3 / 128, (BB * S_CTX) / 128, 1), 256>>>(
        context, W_qkv_ctx, b_qkv_ctx, qkv_ctx, BB * S_CTX, Q3, DIM, 0, 0);

    // 2) RMSNorm + RoPE + scatter
    normrope_kernel<<<dim3(NT, BB), 256>>>(qs_in, ks_in, qs_ctx, ks_ctx);

    // 3) Attention
    cudaFuncSetAttribute(attn_kernel,
                         cudaFuncAttributeMaxDynamicSharedMemorySize, SM_ATTN);
    attn_kernel<<<dim3(NT / 128, NH, BB), 256, SM_ATTN>>>();

    // 4) Output projections
    gemm_tf32<<<dim3(DIM / 128, S_IN / 128, BB), 256>>>(
        o + (long long)S_CTX * DIM, W_out_in, b_out_in, out,
        S_IN, DIM, DIM, (long long)NT * DIM, (long long)S_IN * DIM);
    gemm_tf32<<<dim3(DIM / 128, S_CTX / 128, BB), 256>>>(
        o, W_out_ctx, b_out_ctx, out + (long long)BB * S_IN * DIM,
        S_CTX, DIM, DIM, (long long)NT * DIM, (long long)S_CTX * DIM);
}

// round 5
// speedup vs baseline: 3.2234x; 1.0467x over previous
#include <cuda_runtime.h>
#include <math.h>
#include <stdint.h>

#define NH    12
#define HD    128
#define DIM   1536
#define BB    2
#define S_IN  2048
#define S_CTX 256
#define NT    (S_IN + S_CTX)   // 2304
#define Q3    (3 * DIM)        // 4608
#define NKT   (NT / 64)        // 36

// ------------------------- scratch (no cudaMalloc allowed) -------------------
static __device__ float g_qkv_in [(size_t)BB * S_IN  * Q3];
static __device__ float g_qkv_ctx[(size_t)BB * S_CTX * Q3];
static __device__ float g_q[(size_t)BB * NH * NT * HD];
static __device__ float g_k[(size_t)BB * NH * NT * HD];
static __device__ float g_v[(size_t)BB * NH * NT * HD];   // stored [b][h][d][n]!
static __device__ float g_o[(size_t)BB * NT * DIM];
static __device__ float g_wt[18874368];          // transposed weights
static __device__ float g_in_r [(size_t)BB * S_IN  * DIM];  // rounded input
static __device__ float g_ctx_r[(size_t)BB * S_CTX * DIM];  // rounded context

#define WT_QKV_IN  0
#define WT_QKV_CTX 7077888
#define WT_OUT_IN  14155776
#define WT_OUT_CTX 16515072

// ------------------------- helpers -------------------------------------------
__device__ __forceinline__ float to_tf32(float x) {
    float r;
    asm("cvt.rna.tf32.f32 %0, %1;" : "=f"(r) : "f"(x));
    return r;
}

__device__ __forceinline__ unsigned smem_u32(const void* p) {
    unsigned a;
    asm("{ .reg .u64 t; cvta.to.shared.u64 t, %1; cvt.u32.u64 %0, t; }"
        : "=r"(a) : "l"(p));
    return a;
}

__device__ __forceinline__ void cp16(unsigned s, const void* g) {
    unsigned long long ga;
    asm("cvta.to.global.u64 %0, %1;" : "=l"(ga) : "l"(g));
    asm volatile("cp.async.cg.shared.global [%0], [%1], 16;"
                 :: "r"(s), "l"(ga));
}
#define CP_COMMIT() asm volatile("cp.async.commit_group;" ::: "memory")
#define CP_WAIT0()  asm volatile("cp.async.wait_group 0;" ::: "memory")
#define CP_WAIT1()  asm volatile("cp.async.wait_group 1;" ::: "memory")
#define CP_WAIT2()  asm volatile("cp.async.wait_group 2;" ::: "memory")

__device__ __forceinline__ void ldsm4(unsigned* r, unsigned addr) {
    asm volatile("ldmatrix.sync.aligned.m8n8.x4.shared.b16 {%0,%1,%2,%3}, [%4];"
        : "=r"(r[0]), "=r"(r[1]), "=r"(r[2]), "=r"(r[3]) : "r"(addr));
}

__device__ __forceinline__ void mma8(float* c, const unsigned* a,
                                     unsigned b0, unsigned b1) {
    asm volatile(
        "mma.sync.aligned.m16n8k8.row.col.f32.tf32.tf32.f32 "
        "{%0,%1,%2,%3}, {%4,%5,%6,%7}, {%8,%9}, {%0,%1,%2,%3};"
        : "+f"(c[0]), "+f"(c[1]), "+f"(c[2]), "+f"(c[3])
        : "r"(a[0]), "r"(a[1]), "r"(a[2]), "r"(a[3]), "r"(b0), "r"(b1));
}

// fast exp via MUFU: exp(x) = 2^(x*log2e); exact enough (~1e-6) for softmax
__device__ __forceinline__ float fexp(float x) {
    float r;
    asm("ex2.approx.ftz.f32 %0, %1;" : "=f"(r) : "f"(x * 1.4426950408889634f));
    return r;
}

// ------------------------- round-copy (pre-round A operands) -----------------
__global__ void __launch_bounds__(256)
round_copy(const float* __restrict__ in, float* __restrict__ out, int n4)
{
    int i = blockIdx.x * 256 + threadIdx.x;
    if (i < n4) {
        float4 v = ((const float4*)in)[i];
        v.x = to_tf32(v.x); v.y = to_tf32(v.y);
        v.z = to_tf32(v.z); v.w = to_tf32(v.w);
        ((float4*)out)[i] = v;
    }
}

// ------------------------- weight transpose + tf32 round ---------------------
__global__ void __launch_bounds__(256)
transpose_tf32(const float* __restrict__ W, float* __restrict__ Wt,
               int K, int N)
{
    __shared__ float t[32][33];
    int x  = blockIdx.x * 32 + threadIdx.x;
    int y0 = blockIdx.y * 32 + threadIdx.y;
    #pragma unroll
    for (int j = 0; j < 4; j++)
        t[threadIdx.y + j * 8][threadIdx.x] = W[(size_t)(y0 + j * 8) * N + x];
    __syncthreads();
    int x2 = blockIdx.y * 32 + threadIdx.x;
    int y2 = blockIdx.x * 32 + threadIdx.y;
    #pragma unroll
    for (int j = 0; j < 4; j++)
        Wt[(size_t)(y2 + j * 8) * K + x2] =
            to_tf32(t[threadIdx.x][threadIdx.y + j * 8]);
}

// ------------------------- TF32 GEMM (cp.async + ldmatrix) -------------------
// C[M,N] = A[M,K] @ Wt[N,K]^T + bias. CTA 128x256, warp 64x64, k-chunk 16,
// 4-stage cp.async ring. A and Wt pre-rounded to tf32.
// Smem per stage: As 128x20 fl + Bs 256x20 fl = 30720 B; 4 stages = 120 KB.
#define G_STAGE 30720
#define SM_GEMM (4 * G_STAGE)

__global__ void __launch_bounds__(256, 1)
gemm_tc32(const float* __restrict__ A, const float* __restrict__ Wt,
          const float* __restrict__ bias, float* __restrict__ C,
          int M, int N, int K, long long sA, long long sC)
{
    extern __shared__ char smem[];
    const unsigned sb = smem_u32(smem);

    const int tid  = threadIdx.x;
    const int lane = tid & 31;
    const int wid  = tid >> 5;
    const int wm   = (wid & 1) * 64;
    const int wn   = (wid >> 1) * 64;
    const int l4   = lane >> 2;
    const int lm   = lane & 3;

    const float* Ap = A + blockIdx.z * sA + (long long)blockIdx.y * 128 * K;
    const float* Wp = Wt + (long long)blockIdx.x * 256 * K;
    const float* bp = bias + (long long)blockIdx.x * 256;
    float*       Cp = C + blockIdx.z * sC + (long long)blockIdx.y * 128 * N
                        + (long long)blockIdx.x * 256;

    const int NCH = K / 16;

    // loader assignments
    const int a_row = tid >> 2, a_ch = tid & 3;       // + 64-row step (j)
    // issue one chunk into stage st
    auto issue = [&](int c, int st) {
        unsigned as = sb + st * G_STAGE;
        unsigned bs = as + 10240;
        const float* ag = Ap + (size_t)a_row * K + c * 16 + a_ch * 4;
        #pragma unroll
        for (int j = 0; j < 2; j++)
            cp16(as + (a_row + j * 64) * 80 + a_ch * 16, ag + (size_t)j * 64 * K);
        const float* bg = Wp + (size_t)a_row * K + c * 16 + a_ch * 4;
        #pragma unroll
        for (int j = 0; j < 4; j++)
            cp16(bs + (a_row + j * 64) * 80 + a_ch * 16, bg + (size_t)j * 64 * K);
    };

    float acc[4][8][4];
    #pragma unroll
    for (int mi = 0; mi < 4; mi++)
        #pragma unroll
        for (int ni = 0; ni < 8; ni++)
            #pragma unroll
            for (int c = 0; c < 4; c++) acc[mi][ni][c] = 0.f;

    issue(0, 0); CP_COMMIT();
    issue(1, 1); CP_COMMIT();
    issue(2, 2); CP_COMMIT();

    // fragment address bases (lane-dependent)
    const unsigned a_off = (wm + (lane & 7) + ((lane >> 3) & 1) * 8) * 80
                         + (lane >> 4) * 16;
    const unsigned b_off = 10240 + (wn + (lane & 7)) * 80 + (lane >> 3) * 16;

    for (int i = 0; i < NCH; i++) {
        CP_WAIT2();
        __syncthreads();
        if (i + 3 < NCH) issue(i + 3, (i + 3) & 3);
        CP_COMMIT();

        unsigned st = sb + (i & 3) * G_STAGE;
        unsigned af[4][2][4];
        #pragma unroll
        for (int mi = 0; mi < 4; mi++)
            #pragma unroll
            for (int ks = 0; ks < 2; ks++)
                ldsm4(af[mi][ks], st + a_off + mi * 16 * 80 + ks * 32);
        #pragma unroll
        for (int ni = 0; ni < 8; ni++) {
            unsigned bf[4];
            ldsm4(bf, st + b_off + ni * 8 * 80);
            #pragma unroll
            for (int mi = 0; mi < 4; mi++) {
                mma8(acc[mi][ni], af[mi][0], bf[0], bf[1]);
                mma8(acc[mi][ni], af[mi][1], bf[2], bf[3]);
            }
        }
        __syncthreads();
    }

    #pragma unroll
    for (int mi = 0; mi < 4; mi++) {
        #pragma unroll
        for (int ni = 0; ni < 8; ni++) {
            int r0 = wm + 16 * mi + l4;
            int c0 = wn + 8 * ni + 2 * lm;
            float bx = bp[c0], by = bp[c0 + 1];
            *(float2*)(Cp + (long long)r0 * N + c0) =
                make_float2(acc[mi][ni][0] + bx, acc[mi][ni][1] + by);
            *(float2*)(Cp + (long long)(r0 + 8) * N + c0) =
                make_float2(acc[mi][ni][2] + bx, acc[mi][ni][3] + by);
        }
    }
}

// ----------------- RMSNorm + RoPE + scatter ----------------------------------
// Q: pre-scaled by 128^-0.5, rounded tf32, layout [b][h][n][d]
// K: rounded tf32, layout [b][h][n][d]
// V: rounded tf32, TRANSPOSED layout [b][h][d][n]
__global__ void __launch_bounds__(256)
normrope_kernel(const float* __restrict__ qs_in, const float* __restrict__ ks_in,
                const float* __restrict__ qs_ctx, const float* __restrict__ ks_ctx)
{
    const int pos = blockIdx.x;
    const int b   = blockIdx.y;
    const int t   = threadIdx.x;

    __shared__ float buf[DIM];
    __shared__ float red[8];
    __shared__ float cosv[64], sinv[64];

    const float* src; const float* qs; const float* ks;
    if (pos < S_CTX) {
        src = g_qkv_ctx + ((long long)b * S_CTX + pos) * Q3;
        qs = qs_ctx; ks = ks_ctx;
    } else {
        src = g_qkv_in + ((long long)b * S_IN + (pos - S_CTX)) * Q3;
        qs = qs_in; ks = ks_in;
    }

    if (t < 64) {
        double ang = (double)pos * pow(10000.0, -(double)t / 64.0);
        cosv[t] = (float)cos(ang);
        sinv[t] = (float)sin(ang);
    }

    const float qscale = 0.088388347648318447f;   // 128^-0.5

    #pragma unroll
    for (int which = 0; which < 2; which++) {
        const float* x  = src + which * DIM;
        const float* sc = which ? ks : qs;
        float v[6];
        float local = 0.f;
        #pragma unroll
        for (int i = 0; i < 6; i++) {
            v[i] = x[t + i * 256];
            local = fmaf(v[i], v[i], local);
        }
        #pragma unroll
        for (int off = 16; off; off >>= 1)
            local += __shfl_xor_sync(0xffffffffu, local, off);
        if ((t & 31) == 0) red[t >> 5] = local;
        __syncthreads();
        float tot = red[0] + red[1] + red[2] + red[3]
                  + red[4] + red[5] + red[6] + red[7];
        float r = rsqrtf(tot * (1.0f / DIM) + 1e-6f);
        #pragma unroll
        for (int i = 0; i < 6; i++)
            buf[t + i * 256] = v[i] * r * sc[t + i * 256];
        __syncthreads();

        float* dst = which ? g_k : g_q;
        float post = which ? 1.0f : qscale;
        #pragma unroll
        for (int i = 0; i < 6; i++) {
            int e = t + i * 256;
            int hh = e >> 7, d = e & 127, j = d & 63;
            float c = cosv[j], sn = sinv[j];
            float y = (d < 64) ? (buf[e] * c - buf[e + 64] * sn)
                               : (buf[e] * c + buf[e - 64] * sn);
            dst[(((long long)b * NH + hh) * NT + pos) * HD + d] =
                to_tf32(y * post);
        }
        __syncthreads();
    }

    // V: transposed scatter [b][h][d][n], rounded
    #pragma unroll
    for (int i = 0; i < 6; i++) {
        int e = t + i * 256;
        int hh = e >> 7, d = e & 127;
        g_v[(((long long)b * NH + hh) * HD + d) * NT + pos] =
            to_tf32(src[2 * DIM + e]);
    }
}

// ------------------------- TF32 flash attention ------------------------------
// 128-query tile, 8 warps x 16q. K tiles of 64 keys, double-buffered cp.async;
// V (d-major) single-buffered cp.async; ldmatrix for all fragments.
// Smem floats: Qs[128][132], Ks[2][64][132], Vt[128][68], Ps[128][68]
#define ATT_QS   0
#define ATT_KS   67584
#define ATT_VT   135168
#define ATT_PS   169984
#define SM_ATTN  204800

__global__ void __launch_bounds__(256, 1)
attn_kernel(void)
{
    extern __shared__ char smem[];
    const unsigned sb = smem_u32(smem);

    const int qt = blockIdx.x, h = blockIdx.y, b = blockIdx.z;
    const long long base = (((long long)b * NH + h) * NT) * HD;
    const float* Qg  = g_q + base + (long long)qt * 128 * HD;
    const float* Kg  = g_k + base;
    const float* Vtg = g_v + (((long long)b * NH + h) * HD) * NT;  // [d][n]

    const int tid  = threadIdx.x;
    const int lane = tid & 31;
    const int wid  = tid >> 5;
    const int l4   = lane >> 2;
    const int lm   = lane & 3;
    const int q0   = wid * 16;

    // loaders ----------------------------------------------------------------
    auto load_K = [&](int kt, int bf) {
        unsigned dst = sb + ATT_KS + bf * 33792;
        const float* src = Kg + (long long)kt * 64 * HD;
        #pragma unroll
        for (int it = 0; it < 8; it++) {
            int lin = tid + it * 256;
            int key = lin >> 5, ch = lin & 31;
            cp16(dst + key * 528 + ch * 16, src + key * 128 + ch * 4);
        }
    };
    auto load_V = [&](int kt) {
        unsigned dst = sb + ATT_VT;
        const float* src = Vtg + kt * 64;
        #pragma unroll
        for (int it = 0; it < 8; it++) {
            int lin = tid + it * 256;
            int row = lin >> 4, ch = lin & 15;
            cp16(dst + row * 272 + ch * 16, src + (long long)row * NT + ch * 4);
        }
    };

    // prologue: Q, K0, V0
    #pragma unroll
    for (int it = 0; it < 16; it++) {
        int lin = tid + it * 256;
        int row = lin >> 5, ch = lin & 31;
        cp16(sb + ATT_QS + row * 528 + ch * 16, Qg + row * 128 + ch * 4);
    }
    CP_COMMIT();
    load_K(0, 0); CP_COMMIT();
    load_V(0);    CP_COMMIT();
    CP_WAIT2();          // Q ready
    __syncthreads();

    float O[16][4];
    #pragma unroll
    for (int ni = 0; ni < 16; ni++)
        #pragma unroll
        for (int c = 0; c < 4; c++) O[ni][c] = 0.f;
    float m0 = -1e30f, m1 = -1e30f, l0 = 0.f, l1 = 0.f;

    // fragment bases
    const unsigned qa = sb + ATT_QS
        + (q0 + (lane & 7) + ((lane >> 3) & 1) * 8) * 528 + (lane >> 4) * 16;
    const unsigned kb_lane = (lane & 7) * 528 + (lane >> 3) * 16;
    const unsigned pa = sb + ATT_PS
        + (q0 + (lane & 7) + ((lane >> 3) & 1) * 8) * 272 + (lane >> 4) * 16;
    const unsigned vb_lane = ((lane & 7) + ((lane >> 4) << 3)) * 272
        + ((lane >> 3) & 1) * 16;

    for (int kt = 0; kt < NKT; kt++) {
        CP_WAIT1();      // K(kt) ready (V(kt) may pend)
        __syncthreads();

        // ---- S = Q @ K^T -----------------------------------------------------
        const unsigned kbase = sb + ATT_KS + (kt & 1) * 33792 + kb_lane;
        float s[8][4];
        #pragma unroll
        for (int ni = 0; ni < 8; ni++)
            #pragma unroll
            for (int c = 0; c < 4; c++) s[ni][c] = 0.f;

        #pragma unroll
        for (int kp = 0; kp < 8; kp++) {
            unsigned a0[4], a1[4];
            ldsm4(a0, qa + kp * 64);
            ldsm4(a1, qa + kp * 64 + 32);
            #pragma unroll
            for (int ni = 0; ni < 8; ni++) {
                unsigned bf[4];
                ldsm4(bf, kbase + ni * 8 * 528 + kp * 64);
                mma8(s[ni], a0, bf[0], bf[1]);
                mma8(s[ni], a1, bf[2], bf[3]);
            }
        }

        // prefetch K(kt+1) (other buffer) — overlaps softmax + PV
        if (kt + 1 < NKT) load_K(kt + 1, (kt + 1) & 1);
        CP_COMMIT();

        // ---- online softmax --------------------------------------------------
        float mx0 = -1e30f, mx1 = -1e30f;
        #pragma unroll
        for (int ni = 0; ni < 8; ni++) {
            mx0 = fmaxf(mx0, fmaxf(s[ni][0], s[ni][1]));
            mx1 = fmaxf(mx1, fmaxf(s[ni][2], s[ni][3]));
        }
        mx0 = fmaxf(mx0, __shfl_xor_sync(0xffffffffu, mx0, 1));
        mx0 = fmaxf(mx0, __shfl_xor_sync(0xffffffffu, mx0, 2));
        mx1 = fmaxf(mx1, __shfl_xor_sync(0xffffffffu, mx1, 1));
        mx1 = fmaxf(mx1, __shfl_xor_sync(0xffffffffu, mx1, 2));

        float mn0 = fmaxf(m0, mx0), mn1 = fmaxf(m1, mx1);
        float al0 = fexp(m0 - mn0), al1 = fexp(m1 - mn1);
        float ls0 = 0.f, ls1 = 0.f;
        #pragma unroll
        for (int ni = 0; ni < 8; ni++) {
            float p0 = fexp(s[ni][0] - mn0);
            float p1 = fexp(s[ni][1] - mn0);
            float p2 = fexp(s[ni][2] - mn1);
            float p3 = fexp(s[ni][3] - mn1);
            ls0 += p0 + p1; ls1 += p2 + p3;
            int cc = ni * 8 + lm * 2;
            *(float2*)(smem + ATT_PS + ((q0 + l4) * 68 + cc) * 4) =
                make_float2(to_tf32(p0), to_tf32(p1));
            *(float2*)(smem + ATT_PS + ((q0 + l4 + 8) * 68 + cc) * 4) =
                make_float2(to_tf32(p2), to_tf32(p3));
        }
        ls0 += __shfl_xor_sync(0xffffffffu, ls0, 1);
        ls0 += __shfl_xor_sync(0xffffffffu, ls0, 2);
        ls1 += __shfl_xor_sync(0xffffffffu, ls1, 1);
        ls1 += __shfl_xor_sync(0xffffffffu, ls1, 2);
        l0 = l0 * al0 + ls0;  m0 = mn0;
        l1 = l1 * al1 + ls1;  m1 = mn1;
        #pragma unroll
        for (int ni = 0; ni < 16; ni++) {
            O[ni][0] *= al0; O[ni][1] *= al0;
            O[ni][2] *= al1; O[ni][3] *= al1;
        }

        // ---- wait V(kt) ------------------------------------------------------
        if (kt + 1 < NKT) { CP_WAIT1(); } else { CP_WAIT0(); }
        __syncthreads();

        // ---- O += P @ V ------------------------------------------------------
        const unsigned vbase = sb + ATT_VT + vb_lane;
        #pragma unroll
        for (int ks = 0; ks < 8; ks++) {
            unsigned a[4];
            ldsm4(a, pa + ks * 32);
            #pragma unroll
            for (int nip = 0; nip < 8; nip++) {
                unsigned bf[4];
                ldsm4(bf, vbase + nip * 16 * 272 + ks * 32);
                mma8(O[2 * nip],     a, bf[0], bf[1]);
                mma8(O[2 * nip + 1], a, bf[2], bf[3]);
            }
        }
        __syncthreads();    // all warps done reading Vt
        if (kt + 1 < NKT) { load_V(kt + 1); CP_COMMIT(); }
    }

    // epilogue: normalize, round (for out-proj cp.async), store
    float inv0 = 1.0f / l0, inv1 = 1.0f / l1;
    long long r0 = (long long)qt * 128 + q0 + l4;
    float* op0 = g_o + ((long long)b * NT + r0) * DIM + h * HD;
    float* op1 = g_o + ((long long)b * NT + r0 + 8) * DIM + h * HD;
    #pragma unroll
    for (int ni = 0; ni < 16; ni++) {
        int cc = ni * 8 + lm * 2;
        *(float2*)(op0 + cc) = make_float2(to_tf32(O[ni][0] * inv0),
                                           to_tf32(O[ni][1] * inv0));
        *(float2*)(op1 + cc) = make_float2(to_tf32(O[ni][2] * inv1),
                                           to_tf32(O[ni][3] * inv1));
    }
}

// ------------------------- launch --------------------------------------------
extern "C" void kernel_launch(void* const* d_in, const int* in_sizes, int n_in,
                              void* d_out, int out_size)
{
    (void)in_sizes; (void)n_in; (void)out_size;

    const float* input     = (const float*)d_in[0];
    const float* context   = (const float*)d_in[1];
    const float* W_qkv_in  = (const float*)d_in[2];
    const float* b_qkv_in  = (const float*)d_in[3];
    const float* W_qkv_ctx = (const float*)d_in[4];
    const float* b_qkv_ctx = (const float*)d_in[5];
    const float* qs_in     = (const float*)d_in[6];
    const float* ks_in     = (const float*)d_in[7];
    const float* qs_ctx    = (const float*)d_in[8];
    const float* ks_ctx    = (const float*)d_in[9];
    const float* W_out_in  = (const float*)d_in[10];
    const float* b_out_in  = (const float*)d_in[11];
    const float* W_out_ctx = (const float*)d_in[12];
    const float* b_out_ctx = (const float*)d_in[13];
    float* out = (float*)d_out;

    float *qkv_in, *qkv_ctx, *o, *wt, *in_r, *ctx_r;
    cudaGetSymbolAddress((void**)&qkv_in,  g_qkv_in);
    cudaGetSymbolAddress((void**)&qkv_ctx, g_qkv_ctx);
    cudaGetSymbolAddress((void**)&o,       g_o);
    cudaGetSymbolAddress((void**)&wt,      g_wt);
    cudaGetSymbolAddress((void**)&in_r,    g_in_r);
    cudaGetSymbolAddress((void**)&ctx_r,   g_ctx_r);

    cudaFuncSetAttribute(gemm_tc32,
                         cudaFuncAttributeMaxDynamicSharedMemorySize, SM_GEMM);
    cudaFuncSetAttribute(attn_kernel,
                         cudaFuncAttributeMaxDynamicSharedMemorySize, SM_ATTN);

    // 0) pre-round A operands; transpose + round weights
    {
        int n4 = BB * S_IN * DIM / 4;
        round_copy<<<(n4 + 255) / 256, 256>>>(input, in_r, n4);
        int m4 = BB * S_CTX * DIM / 4;
        round_copy<<<(m4 + 255) / 256, 256>>>(context, ctx_r, m4);
    }
    transpose_tf32<<<dim3(Q3 / 32, DIM / 32), dim3(32, 8)>>>(
        W_qkv_in, wt + WT_QKV_IN, DIM, Q3);
    transpose_tf32<<<dim3(Q3 / 32, DIM / 32), dim3(32, 8)>>>(
        W_qkv_ctx, wt + WT_QKV_CTX, DIM, Q3);
    transpose_tf32<<<dim3(DIM / 32, DIM / 32), dim3(32, 8)>>>(
        W_out_in, wt + WT_OUT_IN, DIM, DIM);
    transpose_tf32<<<dim3(DIM / 32, DIM / 32), dim3(32, 8)>>>(
        W_out_ctx, wt + WT_OUT_CTX, DIM, DIM);

    // 1) QKV projections
    gemm_tc32<<<dim3(Q3 / 256, (BB * S_IN) / 128, 1), 256, SM_GEMM>>>(
        in_r, wt + WT_QKV_IN, b_qkv_in, qkv_in, BB * S_IN, Q3, DIM, 0, 0);
    gemm_tc32<<<dim3(Q3 / 256, (BB * S_CTX) / 128, 1), 256, SM_GEMM>>>(
        ctx_r, wt + WT_QKV_CTX, b_qkv_ctx, qkv_ctx, BB * S_CTX, Q3, DIM, 0, 0);

    // 2) RMSNorm + RoPE + scatter (Q scaled+rounded, K rounded, V transposed)
    normrope_kernel<<<dim3(NT, BB), 256>>>(qs_in, ks_in, qs_ctx, ks_ctx);

    // 3) Attention
    attn_kernel<<<dim3(NT / 128, NH, BB), 256, SM_ATTN>>>();

    // 4) Output projections
    gemm_tc32<<<dim3(DIM / 256, S_IN / 128, BB), 256, SM_GEMM>>>(
        o + (long long)S_CTX * DIM, wt + WT_OUT_IN, b_out_in, out,
        S_IN, DIM, DIM, (long long)NT * DIM, (long long)S_IN * DIM);
    gemm_tc32<<<dim3(DIM / 256, S_CTX / 128, BB), 256, SM_GEMM>>>(
        o, wt + WT_OUT_CTX, b_out_ctx, out + (long long)BB * S_IN * DIM,
        S_CTX, DIM, DIM, (long long)NT * DIM, (long long)S_CTX * DIM);
}

// round 6
// speedup vs baseline: 5.0693x; 1.5727x over previous
#include <cuda_runtime.h>
#include <cuda_fp16.h>
#include <math.h>
#include <stdint.h>

#define NH    12
#define HD    128
#define DIM   1536
#define BB    2
#define S_IN  2048
#define S_CTX 256
#define NT    (S_IN + S_CTX)   // 2304
#define Q3    (3 * DIM)        // 4608
#define NKT   (NT / 64)        // 36

// ------------------------- scratch (no cudaMalloc allowed) -------------------
static __device__ float  g_qkv_in [(size_t)BB * S_IN  * Q3];
static __device__ float  g_qkv_ctx[(size_t)BB * S_CTX * Q3];
static __device__ __half g_q[(size_t)BB * NH * NT * HD];   // scaled, [b][h][n][d]
static __device__ __half g_k[(size_t)BB * NH * NT * HD];   // [b][h][n][d]
static __device__ __half g_v[(size_t)BB * NH * NT * HD];   // [b][h][d][n] (transposed)
static __device__ __half g_o[(size_t)BB * NT * DIM];
static __device__ __half g_wt[18874368];                   // transposed weights (half)
static __device__ __half g_in_r [(size_t)BB * S_IN  * DIM];
static __device__ __half g_ctx_r[(size_t)BB * S_CTX * DIM];

#define WT_QKV_IN  0
#define WT_QKV_CTX 7077888
#define WT_OUT_IN  14155776
#define WT_OUT_CTX 16515072

// ------------------------- helpers -------------------------------------------
__device__ __forceinline__ unsigned smem_u32(const void* p) {
    unsigned a;
    asm("{ .reg .u64 t; cvta.to.shared.u64 t, %1; cvt.u32.u64 %0, t; }"
        : "=r"(a) : "l"(p));
    return a;
}

__device__ __forceinline__ void cp16(unsigned s, const void* g) {
    unsigned long long ga;
    asm("cvta.to.global.u64 %0, %1;" : "=l"(ga) : "l"(g));
    asm volatile("cp.async.cg.shared.global [%0], [%1], 16;"
                 :: "r"(s), "l"(ga));
}
#define CP_COMMIT() asm volatile("cp.async.commit_group;" ::: "memory")
#define CP_WAIT0()  asm volatile("cp.async.wait_group 0;" ::: "memory")
#define CP_WAIT1()  asm volatile("cp.async.wait_group 1;" ::: "memory")
#define CP_WAIT2()  asm volatile("cp.async.wait_group 2;" ::: "memory")

__device__ __forceinline__ void ldsm4(unsigned* r, unsigned addr) {
    asm volatile("ldmatrix.sync.aligned.m8n8.x4.shared.b16 {%0,%1,%2,%3}, [%4];"
        : "=r"(r[0]), "=r"(r[1]), "=r"(r[2]), "=r"(r[3]) : "r"(addr));
}

// f16 MMA, fp32 accumulate: D(16x8) += A(16x16) @ B(16x8)
__device__ __forceinline__ void mma16(float* c, const unsigned* a,
                                      unsigned b0, unsigned b1) {
    asm volatile(
        "mma.sync.aligned.m16n8k16.row.col.f32.f16.f16.f32 "
        "{%0,%1,%2,%3}, {%4,%5,%6,%7}, {%8,%9}, {%0,%1,%2,%3};"
        : "+f"(c[0]), "+f"(c[1]), "+f"(c[2]), "+f"(c[3])
        : "r"(a[0]), "r"(a[1]), "r"(a[2]), "r"(a[3]), "r"(b0), "r"(b1));
}

// fast exp via MUFU (x <= ~0 in softmax)
__device__ __forceinline__ float fexp(float x) {
    float r;
    asm("ex2.approx.ftz.f32 %0, %1;" : "=f"(r) : "f"(x * 1.4426950408889634f));
    return r;
}

// ------------------------- half-copy (pre-convert A operands) ----------------
__global__ void __launch_bounds__(256)
half_copy(const float* __restrict__ in, __half* __restrict__ out, int n4)
{
    int i = blockIdx.x * 256 + threadIdx.x;
    if (i < n4) {
        float4 v = ((const float4*)in)[i];
        ((__half2*)out)[2 * i]     = __floats2half2_rn(v.x, v.y);
        ((__half2*)out)[2 * i + 1] = __floats2half2_rn(v.z, v.w);
    }
}

// ------------------------- weight transpose -> half --------------------------
__global__ void __launch_bounds__(256)
transpose_half(const float* __restrict__ W, __half* __restrict__ Wt,
               int K, int N)
{
    __shared__ float t[32][33];
    int x  = blockIdx.x * 32 + threadIdx.x;
    int y0 = blockIdx.y * 32 + threadIdx.y;
    #pragma unroll
    for (int j = 0; j < 4; j++)
        t[threadIdx.y + j * 8][threadIdx.x] = W[(size_t)(y0 + j * 8) * N + x];
    __syncthreads();
    int x2 = blockIdx.y * 32 + threadIdx.x;
    int y2 = blockIdx.x * 32 + threadIdx.y;
    #pragma unroll
    for (int j = 0; j < 4; j++)
        Wt[(size_t)(y2 + j * 8) * K + x2] =
            __float2half_rn(t[threadIdx.x][threadIdx.y + j * 8]);
}

// ------------------------- F16 GEMM (cp.async + ldmatrix + m16n8k16) ---------
// C[M,N] = A[M,K] @ Wt[N,K]^T + bias. CTA 128x256, warp 64x64, k-chunk 32,
// 4-stage cp.async ring. Rows padded to 80B (64B data) -> ldsm conflict-free.
#define G_STAGE 30720
#define SM_GEMM (4 * G_STAGE)

__global__ void __launch_bounds__(256, 1)
gemm_f16(const __half* __restrict__ A, const __half* __restrict__ Wt,
         const float* __restrict__ bias, float* __restrict__ C,
         int M, int N, int K, long long sA, long long sC)
{
    extern __shared__ char smem[];
    const unsigned sb = smem_u32(smem);

    const int tid  = threadIdx.x;
    const int lane = tid & 31;
    const int wid  = tid >> 5;
    const int wm   = (wid & 1) * 64;
    const int wn   = (wid >> 1) * 64;
    const int l4   = lane >> 2;
    const int lm   = lane & 3;

    const __half* Ap = A + blockIdx.z * sA + (long long)blockIdx.y * 128 * K;
    const __half* Wp = Wt + (long long)blockIdx.x * 256 * K;
    const float*  bp = bias + (long long)blockIdx.x * 256;
    float*        Cp = C + blockIdx.z * sC + (long long)blockIdx.y * 128 * N
                         + (long long)blockIdx.x * 256;

    const int NCH = K / 32;

    const int lrow = tid >> 1;
    const int lcb  = (tid & 1) * 32;            // byte offset within 64B row
    auto issue = [&](int c, int st) {
        unsigned as = sb + st * G_STAGE;
        unsigned bs = as + 10240;
        const __half* ag = Ap + (size_t)lrow * K + c * 32 + lcb / 2;
        cp16(as + lrow * 80 + lcb, ag);
        cp16(as + lrow * 80 + lcb + 16, ag + 8);
        #pragma unroll
        for (int j = 0; j < 2; j++) {
            int r = lrow + j * 128;
            const __half* bg = Wp + (size_t)r * K + c * 32 + lcb / 2;
            cp16(bs + r * 80 + lcb, bg);
            cp16(bs + r * 80 + lcb + 16, bg + 8);
        }
    };

    float acc[4][8][4];
    #pragma unroll
    for (int mi = 0; mi < 4; mi++)
        #pragma unroll
        for (int ni = 0; ni < 8; ni++)
            #pragma unroll
            for (int c = 0; c < 4; c++) acc[mi][ni][c] = 0.f;

    issue(0, 0); CP_COMMIT();
    issue(1, 1); CP_COMMIT();
    issue(2, 2); CP_COMMIT();

    const unsigned a_off = (wm + (lane & 15)) * 80 + (lane >> 4) * 16;
    const unsigned b_off = 10240 + (wn + (lane & 15)) * 80 + (lane >> 4) * 16;

    for (int i = 0; i < NCH; i++) {
        CP_WAIT2();
        __syncthreads();
        if (i + 3 < NCH) issue(i + 3, (i + 3) & 3);
        CP_COMMIT();

        unsigned st = sb + (i & 3) * G_STAGE;
        #pragma unroll
        for (int kp = 0; kp < 2; kp++) {
            unsigned af[4][4];
            #pragma unroll
            for (int mi = 0; mi < 4; mi++)
                ldsm4(af[mi], st + a_off + mi * 16 * 80 + kp * 32);
            #pragma unroll
            for (int nb = 0; nb < 4; nb++) {
                unsigned bf[4];
                ldsm4(bf, st + b_off + nb * 16 * 80 + kp * 32);
                #pragma unroll
                for (int mi = 0; mi < 4; mi++) {
                    mma16(acc[mi][2 * nb],     af[mi], bf[0], bf[2]);
                    mma16(acc[mi][2 * nb + 1], af[mi], bf[1], bf[3]);
                }
            }
        }
        __syncthreads();
    }

    #pragma unroll
    for (int mi = 0; mi < 4; mi++) {
        #pragma unroll
        for (int ni = 0; ni < 8; ni++) {
            int r0 = wm + 16 * mi + l4;
            int c0 = wn + 8 * ni + 2 * lm;
            float bx = bp[c0], by = bp[c0 + 1];
            *(float2*)(Cp + (long long)r0 * N + c0) =
                make_float2(acc[mi][ni][0] + bx, acc[mi][ni][1] + by);
            *(float2*)(Cp + (long long)(r0 + 8) * N + c0) =
                make_float2(acc[mi][ni][2] + bx, acc[mi][ni][3] + by);
        }
    }
}

// ----------------- RMSNorm + RoPE + scatter (fp32 -> half) -------------------
// Q: pre-scaled by 128^-0.5, [b][h][n][d]; K: [b][h][n][d]; V: [b][h][d][n]
__global__ void __launch_bounds__(256)
normrope_kernel(const float* __restrict__ qs_in, const float* __restrict__ ks_in,
                const float* __restrict__ qs_ctx, const float* __restrict__ ks_ctx)
{
    const int pos = blockIdx.x;
    const int b   = blockIdx.y;
    const int t   = threadIdx.x;

    __shared__ float buf[DIM];
    __shared__ float red[8];
    __shared__ float cosv[64], sinv[64];

    const float* src; const float* qs; const float* ks;
    if (pos < S_CTX) {
        src = g_qkv_ctx + ((long long)b * S_CTX + pos) * Q3;
        qs = qs_ctx; ks = ks_ctx;
    } else {
        src = g_qkv_in + ((long long)b * S_IN + (pos - S_CTX)) * Q3;
        qs = qs_in; ks = ks_in;
    }

    if (t < 64) {
        double ang = (double)pos * pow(10000.0, -(double)t / 64.0);
        cosv[t] = (float)cos(ang);
        sinv[t] = (float)sin(ang);
    }

    const float qscale = 0.088388347648318447f;   // 128^-0.5

    #pragma unroll
    for (int which = 0; which < 2; which++) {
        const float* x  = src + which * DIM;
        const float* sc = which ? ks : qs;
        float v[6];
        float local = 0.f;
        #pragma unroll
        for (int i = 0; i < 6; i++) {
            v[i] = x[t + i * 256];
            local = fmaf(v[i], v[i], local);
        }
        #pragma unroll
        for (int off = 16; off; off >>= 1)
            local += __shfl_xor_sync(0xffffffffu, local, off);
        if ((t & 31) == 0) red[t >> 5] = local;
        __syncthreads();
        float tot = red[0] + red[1] + red[2] + red[3]
                  + red[4] + red[5] + red[6] + red[7];
        float r = rsqrtf(tot * (1.0f / DIM) + 1e-6f);
        #pragma unroll
        for (int i = 0; i < 6; i++)
            buf[t + i * 256] = v[i] * r * sc[t + i * 256];
        __syncthreads();

        __half* dst = which ? g_k : g_q;
        float post = which ? 1.0f : qscale;
        #pragma unroll
        for (int i = 0; i < 6; i++) {
            int e = t + i * 256;
            int hh = e >> 7, d = e & 127, j = d & 63;
            float c = cosv[j], sn = sinv[j];
            float y = (d < 64) ? (buf[e] * c - buf[e + 64] * sn)
                               : (buf[e] * c + buf[e - 64] * sn);
            dst[(((long long)b * NH + hh) * NT + pos) * HD + d] =
                __float2half_rn(y * post);
        }
        __syncthreads();
    }

    // V: transposed scatter [b][h][d][n]
    #pragma unroll
    for (int i = 0; i < 6; i++) {
        int e = t + i * 256;
        int hh = e >> 7, d = e & 127;
        g_v[(((long long)b * NH + hh) * HD + d) * NT + pos] =
            __float2half_rn(src[2 * DIM + e]);
    }
}

// ------------------------- F16 flash attention -------------------------------
// 192-query tile, 384 thr / 12 warps x 16q. K tiles 64 keys double-buffered,
// V (d-major) single-buffered, all fragments via ldmatrix, m16n8k16 MMA.
// Smem (bytes): Qs 192x272, Ks 2x64x272, Vt 128x144, Ps 192x144
#define ATT_QS   0
#define ATT_KS   52224
#define ATT_VT   87040
#define ATT_PS   105472
#define SM_ATTN  133120

__global__ void __launch_bounds__(384, 1)
attn_kernel(void)
{
    extern __shared__ char smem[];
    const unsigned sb = smem_u32(smem);

    const int qt = blockIdx.x, h = blockIdx.y, b = blockIdx.z;
    const long long base = (((long long)b * NH + h) * NT) * HD;
    const __half* Qg  = g_q + base + (long long)qt * 192 * HD;
    const __half* Kg  = g_k + base;
    const __half* Vtg = g_v + (((long long)b * NH + h) * HD) * NT;   // [d][n]

    const int tid  = threadIdx.x;
    const int lane = tid & 31;
    const int wid  = tid >> 5;        // 0..11
    const int l4   = lane >> 2;
    const int lm   = lane & 3;
    const int q0   = wid * 16;

    auto load_K = [&](int kt, int bf) {
        unsigned dst = sb + ATT_KS + bf * 17408;
        const __half* src = Kg + (size_t)kt * 64 * HD;
        for (int lin = tid; lin < 1024; lin += 384) {
            int row = lin >> 4, ch = lin & 15;
            cp16(dst + row * 272 + ch * 16, src + row * 128 + ch * 8);
        }
    };
    auto load_V = [&](int kt) {
        unsigned dst = sb + ATT_VT;
        const __half* src = Vtg + kt * 64;
        for (int lin = tid; lin < 1024; lin += 384) {
            int row = lin >> 3, ch = lin & 7;
            cp16(dst + row * 144 + ch * 16, src + (size_t)row * NT + ch * 8);
        }
    };

    // prologue: Q, K0, V0
    for (int lin = tid; lin < 3072; lin += 384) {
        int row = lin >> 4, ch = lin & 15;
        cp16(sb + ATT_QS + row * 272 + ch * 16, Qg + row * 128 + ch * 8);
    }
    CP_COMMIT();
    load_K(0, 0); CP_COMMIT();
    load_V(0);    CP_COMMIT();
    CP_WAIT2();
    __syncthreads();

    float O[16][4];
    #pragma unroll
    for (int ni = 0; ni < 16; ni++)
        #pragma unroll
        for (int c = 0; c < 4; c++) O[ni][c] = 0.f;
    float m0 = -1e30f, m1 = -1e30f, l0 = 0.f, l1 = 0.f;

    const unsigned qa = sb + ATT_QS + (q0 + (lane & 15)) * 272 + (lane >> 4) * 16;
    const unsigned kb = (lane & 15) * 272 + (lane >> 4) * 16;
    const unsigned pa = sb + ATT_PS + (q0 + (lane & 15)) * 144 + (lane >> 4) * 16;
    const unsigned vb = (lane & 15) * 144 + (lane >> 4) * 16;

    for (int kt = 0; kt < NKT; kt++) {
        CP_WAIT1();          // K(kt) ready
        __syncthreads();

        // ---- S = Q @ K^T ----
        const unsigned kbase = sb + ATT_KS + (kt & 1) * 17408 + kb;
        float s[8][4];
        #pragma unroll
        for (int ni = 0; ni < 8; ni++)
            #pragma unroll
            for (int c = 0; c < 4; c++) s[ni][c] = 0.f;

        #pragma unroll
        for (int kp = 0; kp < 8; kp++) {
            unsigned a[4];
            ldsm4(a, qa + kp * 32);
            #pragma unroll
            for (int nb = 0; nb < 4; nb++) {
                unsigned bf[4];
                ldsm4(bf, kbase + nb * 16 * 272 + kp * 32);
                mma16(s[2 * nb],     a, bf[0], bf[2]);
                mma16(s[2 * nb + 1], a, bf[1], bf[3]);
            }
        }

        // prefetch K(kt+1) — overlaps softmax + PV
        if (kt + 1 < NKT) load_K(kt + 1, (kt + 1) & 1);
        CP_COMMIT();

        // ---- online softmax ----
        float mx0 = -1e30f, mx1 = -1e30f;
        #pragma unroll
        for (int ni = 0; ni < 8; ni++) {
            mx0 = fmaxf(mx0, fmaxf(s[ni][0], s[ni][1]));
            mx1 = fmaxf(mx1, fmaxf(s[ni][2], s[ni][3]));
        }
        mx0 = fmaxf(mx0, __shfl_xor_sync(0xffffffffu, mx0, 1));
        mx0 = fmaxf(mx0, __shfl_xor_sync(0xffffffffu, mx0, 2));
        mx1 = fmaxf(mx1, __shfl_xor_sync(0xffffffffu, mx1, 1));
        mx1 = fmaxf(mx1, __shfl_xor_sync(0xffffffffu, mx1, 2));

        float mn0 = fmaxf(m0, mx0), mn1 = fmaxf(m1, mx1);
        float al0 = fexp(m0 - mn0), al1 = fexp(m1 - mn1);
        float ls0 = 0.f, ls1 = 0.f;
        #pragma unroll
        for (int ni = 0; ni < 8; ni++) {
            float p0 = fexp(s[ni][0] - mn0);
            float p1 = fexp(s[ni][1] - mn0);
            float p2 = fexp(s[ni][2] - mn1);
            float p3 = fexp(s[ni][3] - mn1);
            ls0 += p0 + p1; ls1 += p2 + p3;
            int cb = (ni * 8 + lm * 2) * 2;    // byte offset of col pair
            *(__half2*)(smem + ATT_PS + (q0 + l4) * 144 + cb) =
                __floats2half2_rn(p0, p1);
            *(__half2*)(smem + ATT_PS + (q0 + l4 + 8) * 144 + cb) =
                __floats2half2_rn(p2, p3);
        }
        ls0 += __shfl_xor_sync(0xffffffffu, ls0, 1);
        ls0 += __shfl_xor_sync(0xffffffffu, ls0, 2);
        ls1 += __shfl_xor_sync(0xffffffffu, ls1, 1);
        ls1 += __shfl_xor_sync(0xffffffffu, ls1, 2);
        l0 = l0 * al0 + ls0;  m0 = mn0;
        l1 = l1 * al1 + ls1;  m1 = mn1;
        #pragma unroll
        for (int ni = 0; ni < 16; ni++) {
            O[ni][0] *= al0; O[ni][1] *= al0;
            O[ni][2] *= al1; O[ni][3] *= al1;
        }

        // ---- wait V(kt); also orders P stores before ldsm reads ----
        if (kt + 1 < NKT) { CP_WAIT1(); } else { CP_WAIT0(); }
        __syncthreads();

        // ---- O += P @ V ----
        #pragma unroll
        for (int kp = 0; kp < 4; kp++) {
            unsigned a[4];
            ldsm4(a, pa + kp * 32);
            #pragma unroll
            for (int g = 0; g < 8; g++) {
                unsigned bf[4];
                ldsm4(bf, sb + ATT_VT + vb + g * 16 * 144 + kp * 32);
                mma16(O[2 * g],     a, bf[0], bf[2]);
                mma16(O[2 * g + 1], a, bf[1], bf[3]);
            }
        }
        __syncthreads();     // all warps done reading Vt
        if (kt + 1 < NKT) { load_V(kt + 1); CP_COMMIT(); }
    }

    // epilogue: normalize, convert to half for the output projections
    float inv0 = 1.0f / l0, inv1 = 1.0f / l1;
    long long r0 = (long long)qt * 192 + q0 + l4;
    __half* op0 = g_o + ((long long)b * NT + r0) * DIM + h * HD;
    __half* op1 = g_o + ((long long)b * NT + r0 + 8) * DIM + h * HD;
    #pragma unroll
    for (int ni = 0; ni < 16; ni++) {
        int cc = ni * 8 + lm * 2;
        *(__half2*)(op0 + cc) = __floats2half2_rn(O[ni][0] * inv0,
                                                  O[ni][1] * inv0);
        *(__half2*)(op1 + cc) = __floats2half2_rn(O[ni][2] * inv1,
                                                  O[ni][3] * inv1);
    }
}

// ------------------------- launch --------------------------------------------
extern "C" void kernel_launch(void* const* d_in, const int* in_sizes, int n_in,
                              void* d_out, int out_size)
{
    (void)in_sizes; (void)n_in; (void)out_size;

    const float* input     = (const float*)d_in[0];
    const float* context   = (const float*)d_in[1];
    const float* W_qkv_in  = (const float*)d_in[2];
    const float* b_qkv_in  = (const float*)d_in[3];
    const float* W_qkv_ctx = (const float*)d_in[4];
    const float* b_qkv_ctx = (const float*)d_in[5];
    const float* qs_in     = (const float*)d_in[6];
    const float* ks_in     = (const float*)d_in[7];
    const float* qs_ctx    = (const float*)d_in[8];
    const float* ks_ctx    = (const float*)d_in[9];
    const float* W_out_in  = (const float*)d_in[10];
    const float* b_out_in  = (const float*)d_in[11];
    const float* W_out_ctx = (const float*)d_in[12];
    const float* b_out_ctx = (const float*)d_in[13];
    float* out = (float*)d_out;

    float *qkv_in, *qkv_ctx;
    __half *o, *wt, *in_r, *ctx_r;
    cudaGetSymbolAddress((void**)&qkv_in,  g_qkv_in);
    cudaGetSymbolAddress((void**)&qkv_ctx, g_qkv_ctx);
    cudaGetSymbolAddress((void**)&o,       g_o);
    cudaGetSymbolAddress((void**)&wt,      g_wt);
    cudaGetSymbolAddress((void**)&in_r,    g_in_r);
    cudaGetSymbolAddress((void**)&ctx_r,   g_ctx_r);

    cudaFuncSetAttribute(gemm_f16,
                         cudaFuncAttributeMaxDynamicSharedMemorySize, SM_GEMM);
    cudaFuncSetAttribute(attn_kernel,
                         cudaFuncAttributeMaxDynamicSharedMemorySize, SM_ATTN);

    // 0) convert A operands to half; transpose + convert weights
    {
        int n4 = BB * S_IN * DIM / 4;
        half_copy<<<(n4 + 255) / 256, 256>>>(input, in_r, n4);
        int m4 = BB * S_CTX * DIM / 4;
        half_copy<<<(m4 + 255) / 256, 256>>>(context, ctx_r, m4);
    }
    transpose_half<<<dim3(Q3 / 32, DIM / 32), dim3(32, 8)>>>(
        W_qkv_in, wt + WT_QKV_IN, DIM, Q3);
    transpose_half<<<dim3(Q3 / 32, DIM / 32), dim3(32, 8)>>>(
        W_qkv_ctx, wt + WT_QKV_CTX, DIM, Q3);
    transpose_half<<<dim3(DIM / 32, DIM / 32), dim3(32, 8)>>>(
        W_out_in, wt + WT_OUT_IN, DIM, DIM);
    transpose_half<<<dim3(DIM / 32, DIM / 32), dim3(32, 8)>>>(
        W_out_ctx, wt + WT_OUT_CTX, DIM, DIM);

    // 1) QKV projections
    gemm_f16<<<dim3(Q3 / 256, (BB * S_IN) / 128, 1), 256, SM_GEMM>>>(
        in_r, wt + WT_QKV_IN, b_qkv_in, qkv_in, BB * S_IN, Q3, DIM, 0, 0);
    gemm_f16<<<dim3(Q3 / 256, (BB * S_CTX) / 128, 1), 256, SM_GEMM>>>(
        ctx_r, wt + WT_QKV_CTX, b_qkv_ctx, qkv_ctx, BB * S_CTX, Q3, DIM, 0, 0);

    // 2) RMSNorm + RoPE + scatter (half outputs; Q scaled; V transposed)
    normrope_kernel<<<dim3(NT, BB), 256>>>(qs_in, ks_in, qs_ctx, ks_ctx);

    // 3) Attention
    attn_kernel<<<dim3(NT / 192, NH, BB), 384, SM_ATTN>>>();

    // 4) Output projections
    gemm_f16<<<dim3(DIM / 256, S_IN / 128, BB), 256, SM_GEMM>>>(
        o + (long long)S_CTX * DIM, wt + WT_OUT_IN, b_out_in, out,
        S_IN, DIM, DIM, (long long)NT * DIM, (long long)S_IN * DIM);
    gemm_f16<<<dim3(DIM / 256, S_CTX / 128, BB), 256, SM_GEMM>>>(
        o, wt + WT_OUT_CTX, b_out_ctx, out + (long long)BB * S_IN * DIM,
        S_CTX, DIM, DIM, (long long)NT * DIM, (long long)S_CTX * DIM);
}

// round 8
// speedup vs baseline: 5.5783x; 1.1004x over previous
#include <cuda_runtime.h>
#include <cuda_fp16.h>
#include <math.h>
#include <stdint.h>

#define NH    12
#define HD    128
#define DIM   1536
#define BB    2
#define S_IN  2048
#define S_CTX 256
#define NT    (S_IN + S_CTX)   // 2304
#define Q3    (3 * DIM)        // 4608
#define NKT   (NT / 64)        // 36

// ------------------------- scratch (no cudaMalloc allowed) -------------------
static __device__ __half g_qkv_in [(size_t)BB * S_IN  * Q3];
static __device__ __half g_qkv_ctx[(size_t)BB * S_CTX * Q3];
static __device__ __half g_q[(size_t)BB * NH * NT * HD];   // scaled, [b][h][n][d]
static __device__ __half g_k[(size_t)BB * NH * NT * HD];   // [b][h][n][d]
static __device__ __half g_v[(size_t)BB * NH * NT * HD];   // [b][h][d][n]
static __device__ __half g_o[(size_t)BB * NT * DIM];
static __device__ __half g_wt[18874368];                   // transposed weights
static __device__ __half g_in_r [(size_t)BB * S_IN  * DIM];
static __device__ __half g_ctx_r[(size_t)BB * S_CTX * DIM];

#define WT_QKV_IN  0
#define WT_QKV_CTX 7077888
#define WT_OUT_IN  14155776
#define WT_OUT_CTX 16515072

// ------------------------- helpers -------------------------------------------
__device__ __forceinline__ unsigned smem_u32(const void* p) {
    unsigned a;
    asm("{ .reg .u64 t; cvta.to.shared.u64 t, %1; cvt.u32.u64 %0, t; }"
        : "=r"(a) : "l"(p));
    return a;
}

__device__ __forceinline__ void cp16(unsigned s, const void* g) {
    unsigned long long ga;
    asm("cvta.to.global.u64 %0, %1;" : "=l"(ga) : "l"(g));
    asm volatile("cp.async.cg.shared.global [%0], [%1], 16;"
                 :: "r"(s), "l"(ga));
}
#define CP_COMMIT() asm volatile("cp.async.commit_group;" ::: "memory")
#define CP_WAIT0()  asm volatile("cp.async.wait_group 0;" ::: "memory")
#define CP_WAIT1()  asm volatile("cp.async.wait_group 1;" ::: "memory")
#define CP_WAIT2()  asm volatile("cp.async.wait_group 2;" ::: "memory")

__device__ __forceinline__ void ldsm4(unsigned* r, unsigned addr) {
    asm volatile("ldmatrix.sync.aligned.m8n8.x4.shared.b16 {%0,%1,%2,%3}, [%4];"
        : "=r"(r[0]), "=r"(r[1]), "=r"(r[2]), "=r"(r[3]) : "r"(addr));
}

__device__ __forceinline__ void mma16(float* c, const unsigned* a,
                                      unsigned b0, unsigned b1) {
    asm volatile(
        "mma.sync.aligned.m16n8k16.row.col.f32.f16.f16.f32 "
        "{%0,%1,%2,%3}, {%4,%5,%6,%7}, {%8,%9}, {%0,%1,%2,%3};"
        : "+f"(c[0]), "+f"(c[1]), "+f"(c[2]), "+f"(c[3])
        : "r"(a[0]), "r"(a[1]), "r"(a[2]), "r"(a[3]), "r"(b0), "r"(b1));
}

__device__ __forceinline__ float fexp(float x) {
    float r;
    asm("ex2.approx.ftz.f32 %0, %1;" : "=f"(r) : "f"(x * 1.4426950408889634f));
    return r;
}

// ------------------------- merged prep kernels -------------------------------
__global__ void __launch_bounds__(256)
half_copy2(const float* __restrict__ in0, __half* __restrict__ out0, int n40,
           const float* __restrict__ in1, __half* __restrict__ out1, int n41)
{
    const float* in = blockIdx.z ? in1 : in0;
    __half* out     = blockIdx.z ? out1 : out0;
    int n4          = blockIdx.z ? n41 : n40;
    int i = blockIdx.x * 256 + threadIdx.x;
    if (i < n4) {
        float4 v = ((const float4*)in)[i];
        ((__half2*)out)[2 * i]     = __floats2half2_rn(v.x, v.y);
        ((__half2*)out)[2 * i + 1] = __floats2half2_rn(v.z, v.w);
    }
}

// W [K=DIM][N] rm -> Wt [N][K] rm (half). z selects which weight.
__global__ void __launch_bounds__(256)
transpose_half4(const float* __restrict__ W0, const float* __restrict__ W1,
                const float* __restrict__ W2, const float* __restrict__ W3)
{
    const float* W; size_t off; int N;
    switch (blockIdx.z) {
        case 0:  W = W0; off = WT_QKV_IN;  N = Q3;  break;
        case 1:  W = W1; off = WT_QKV_CTX; N = Q3;  break;
        case 2:  W = W2; off = WT_OUT_IN;  N = DIM; break;
        default: W = W3; off = WT_OUT_CTX; N = DIM; break;
    }
    if ((int)blockIdx.x * 32 >= N) return;
    __half* Wt = g_wt + off;
    __shared__ float t[32][33];
    int x  = blockIdx.x * 32 + threadIdx.x;   // n
    int y0 = blockIdx.y * 32 + threadIdx.y;   // k
    #pragma unroll
    for (int j = 0; j < 4; j++)
        t[threadIdx.y + j * 8][threadIdx.x] = W[(size_t)(y0 + j * 8) * N + x];
    __syncthreads();
    int x2 = blockIdx.y * 32 + threadIdx.x;   // k
    int y2 = blockIdx.x * 32 + threadIdx.y;   // n
    #pragma unroll
    for (int j = 0; j < 4; j++)
        Wt[(size_t)(y2 + j * 8) * DIM + x2] =
            __float2half_rn(t[threadIdx.x][threadIdx.y + j * 8]);
}

// ------------------------- F16 GEMM core -------------------------------------
// C[128,N-tile 256] = A[128,K] @ Wt[256,K]^T + bias. 4-stage cp.async ring,
// ONE __syncthreads per k-chunk. Warp tile 64x64, m16n8k16.
#define G_STAGE 30720
#define SM_GEMM (4 * G_STAGE)

__device__ __forceinline__ void gstore(__half* p, float x, float y) {
    *(__half2*)p = __floats2half2_rn(x, y);
}
__device__ __forceinline__ void gstore(float* p, float x, float y) {
    *(float2*)p = make_float2(x, y);
}

template <typename OutT>
__device__ __forceinline__ void gemm_core(
    const __half* __restrict__ Ap, const __half* __restrict__ Wp,
    const float* __restrict__ bp, OutT* __restrict__ Cp,
    int K, int N, char* smem)
{
    const unsigned sb = smem_u32(smem);
    const int tid  = threadIdx.x;
    const int lane = tid & 31;
    const int wid  = tid >> 5;
    const int wm   = (wid & 1) * 64;
    const int wn   = (wid >> 1) * 64;
    const int l4   = lane >> 2;
    const int lm   = lane & 3;
    const int NCH  = K / 32;

    const int lrow = tid >> 1;
    const int lcb  = (tid & 1) * 32;
    auto issue = [&](int c, int st) {
        unsigned as = sb + st * G_STAGE;
        unsigned bs = as + 10240;
        const __half* ag = Ap + (size_t)lrow * K + c * 32 + lcb / 2;
        cp16(as + lrow * 80 + lcb, ag);
        cp16(as + lrow * 80 + lcb + 16, ag + 8);
        #pragma unroll
        for (int j = 0; j < 2; j++) {
            int r = lrow + j * 128;
            const __half* bg = Wp + (size_t)r * K + c * 32 + lcb / 2;
            cp16(bs + r * 80 + lcb, bg);
            cp16(bs + r * 80 + lcb + 16, bg + 8);
        }
    };

    float acc[4][8][4];
    #pragma unroll
    for (int mi = 0; mi < 4; mi++)
        #pragma unroll
        for (int ni = 0; ni < 8; ni++)
            #pragma unroll
            for (int c = 0; c < 4; c++) acc[mi][ni][c] = 0.f;

    issue(0, 0); CP_COMMIT();
    issue(1, 1); CP_COMMIT();
    issue(2, 2); CP_COMMIT();

    const unsigned a_off = (wm + (lane & 15)) * 80 + (lane >> 4) * 16;
    const unsigned b_off = 10240 + (wn + (lane & 15)) * 80 + (lane >> 4) * 16;

    for (int i = 0; i < NCH; i++) {
        CP_WAIT2();                       // all but 2 newest groups done
        __syncthreads();                  // slot (i+3)&3 free; slot i&3 ready
        if (i + 3 < NCH) issue(i + 3, (i + 3) & 3);
        CP_COMMIT();

        unsigned st = sb + (i & 3) * G_STAGE;
        #pragma unroll
        for (int kp = 0; kp < 2; kp++) {
            unsigned af[4][4];
            #pragma unroll
            for (int mi = 0; mi < 4; mi++)
                ldsm4(af[mi], st + a_off + mi * 16 * 80 + kp * 32);
            #pragma unroll
            for (int nb = 0; nb < 4; nb++) {
                unsigned bf[4];
                ldsm4(bf, st + b_off + nb * 16 * 80 + kp * 32);
                #pragma unroll
                for (int mi = 0; mi < 4; mi++) {
                    mma16(acc[mi][2 * nb],     af[mi], bf[0], bf[2]);
                    mma16(acc[mi][2 * nb + 1], af[mi], bf[1], bf[3]);
                }
            }
        }
    }

    #pragma unroll
    for (int mi = 0; mi < 4; mi++) {
        #pragma unroll
        for (int ni = 0; ni < 8; ni++) {
            int r0 = wm + 16 * mi + l4;
            int c0 = wn + 8 * ni + 2 * lm;
            float bx = bp[c0], by = bp[c0 + 1];
            gstore(Cp + (size_t)r0 * N + c0,
                   acc[mi][ni][0] + bx, acc[mi][ni][1] + by);
            gstore(Cp + (size_t)(r0 + 8) * N + c0,
                   acc[mi][ni][2] + bx, acc[mi][ni][3] + by);
        }
    }
}

// merged QKV projections: y<32 -> input rows, y>=32 -> ctx rows
__global__ void __launch_bounds__(256, 1)
qkv_gemm(const float* __restrict__ b_in, const float* __restrict__ b_ctx)
{
    extern __shared__ char smem[];
    int y = blockIdx.y;
    const __half* A; const __half* W; const float* bias; __half* C;
    if (y < 32) {
        A = g_in_r + (size_t)y * 128 * DIM;
        W = g_wt + WT_QKV_IN;  bias = b_in;
        C = g_qkv_in + (size_t)y * 128 * Q3;
    } else {
        int y2 = y - 32;
        A = g_ctx_r + (size_t)y2 * 128 * DIM;
        W = g_wt + WT_QKV_CTX; bias = b_ctx;
        C = g_qkv_ctx + (size_t)y2 * 128 * Q3;
    }
    gemm_core<__half>(A, W + (size_t)blockIdx.x * 256 * DIM,
                      bias + blockIdx.x * 256, C + blockIdx.x * 256,
                      DIM, Q3, smem);
}

// merged output projections: y<32 -> input part (b = y>>4), else ctx part
__global__ void __launch_bounds__(256, 1)
out_gemm(const float* __restrict__ b_in, const float* __restrict__ b_ctx,
         float* __restrict__ out)
{
    extern __shared__ char smem[];
    int y = blockIdx.y;
    const __half* A; const __half* W; const float* bias; float* C;
    if (y < 32) {
        int b = y >> 4, yy = y & 15;
        A = g_o + ((size_t)b * NT + S_CTX + yy * 128) * DIM;
        W = g_wt + WT_OUT_IN;  bias = b_in;
        C = out + ((size_t)b * S_IN + yy * 128) * DIM;
    } else {
        int z = y - 32, b = z >> 1, yy = z & 1;
        A = g_o + ((size_t)b * NT + yy * 128) * DIM;
        W = g_wt + WT_OUT_CTX; bias = b_ctx;
        C = out + (size_t)BB * S_IN * DIM + ((size_t)b * S_CTX + yy * 128) * DIM;
    }
    gemm_core<float>(A, W + (size_t)blockIdx.x * 256 * DIM,
                     bias + blockIdx.x * 256, C + blockIdx.x * 256,
                     DIM, DIM, smem);
}

// ----------------- RMSNorm + RoPE + scatter (half -> half) -------------------
__global__ void __launch_bounds__(256)
normrope_kernel(const float* __restrict__ qs_in, const float* __restrict__ ks_in,
                const float* __restrict__ qs_ctx, const float* __restrict__ ks_ctx)
{
    const int pos = blockIdx.x;
    const int b   = blockIdx.y;
    const int t   = threadIdx.x;

    __shared__ float buf[DIM];
    __shared__ float red[8];
    __shared__ float cosv[64], sinv[64];

    const __half* src; const float* qs; const float* ks;
    if (pos < S_CTX) {
        src = g_qkv_ctx + ((size_t)b * S_CTX + pos) * Q3;
        qs = qs_ctx; ks = ks_ctx;
    } else {
        src = g_qkv_in + ((size_t)b * S_IN + (pos - S_CTX)) * Q3;
        qs = qs_in; ks = ks_in;
    }

    if (t < 64) {
        double ang = (double)pos * pow(10000.0, -(double)t / 64.0);
        cosv[t] = (float)cos(ang);
        sinv[t] = (float)sin(ang);
    }

    const float qscale = 0.088388347648318447f;   // 128^-0.5

    #pragma unroll
    for (int which = 0; which < 2; which++) {
        const __half* x  = src + which * DIM;
        const float*  sc = which ? ks : qs;
        float v[6];
        float local = 0.f;
        #pragma unroll
        for (int i = 0; i < 6; i++) {
            v[i] = __half2float(x[t + i * 256]);
            local = fmaf(v[i], v[i], local);
        }
        #pragma unroll
        for (int off = 16; off; off >>= 1)
            local += __shfl_xor_sync(0xffffffffu, local, off);
        if ((t & 31) == 0) red[t >> 5] = local;
        __syncthreads();
        float tot = red[0] + red[1] + red[2] + red[3]
                  + red[4] + red[5] + red[6] + red[7];
        float r = rsqrtf(tot * (1.0f / DIM) + 1e-6f);
        #pragma unroll
        for (int i = 0; i < 6; i++)
            buf[t + i * 256] = v[i] * r * sc[t + i * 256];
        __syncthreads();

        __half* dst = which ? g_k : g_q;
        float post = which ? 1.0f : qscale;
        #pragma unroll
        for (int i = 0; i < 6; i++) {
            int e = t + i * 256;
            int hh = e >> 7, d = e & 127, j = d & 63;
            float c = cosv[j], sn = sinv[j];
            float y = (d < 64) ? (buf[e] * c - buf[e + 64] * sn)
                               : (buf[e] * c + buf[e - 64] * sn);
            dst[(((size_t)b * NH + hh) * NT + pos) * HD + d] =
                __float2half_rn(y * post);
        }
        __syncthreads();
    }

    // V: transposed scatter [b][h][d][n] (plain half copy)
    #pragma unroll
    for (int i = 0; i < 6; i++) {
        int e = t + i * 256;
        int hh = e >> 7, d = e & 127;
        g_v[(((size_t)b * NH + hh) * HD + d) * NT + pos] = src[2 * DIM + e];
    }
}

// ------------------------- F16 flash attention -------------------------------
// 192-query tile, 384 thr / 12 warps. K+V triple-buffered together (one commit
// group per ktile) -> ONE __syncthreads + one wait per ktile. P warp-private.
// Smem: Qs 192x272 | K 3x(64x272) | V 3x(128x144) | Ps 192x144
#define ATT_QS   0
#define ATT_K    52224
#define ATT_V    104448
#define ATT_PS   159744
#define SM_ATTN  187392

__global__ void __launch_bounds__(384, 1)
attn_kernel(void)
{
    extern __shared__ char smem[];
    const unsigned sb = smem_u32(smem);

    const int qt = blockIdx.x, h = blockIdx.y, b = blockIdx.z;
    const size_t base = (((size_t)b * NH + h) * NT) * HD;
    const __half* Qg  = g_q + base + (size_t)qt * 192 * HD;
    const __half* Kg  = g_k + base;
    const __half* Vtg = g_v + (((size_t)b * NH + h) * HD) * NT;   // [d][n]

    const int tid  = threadIdx.x;
    const int lane = tid & 31;
    const int wid  = tid >> 5;        // 0..11
    const int l4   = lane >> 2;
    const int lm   = lane & 3;
    const int q0   = wid * 16;

    auto load_KV = [&](int kt, int slot) {
        unsigned kdst = sb + ATT_K + slot * 17408;
        const __half* ks = Kg + (size_t)kt * 64 * HD;
        for (int lin = tid; lin < 1024; lin += 384) {
            int row = lin >> 4, ch = lin & 15;
            cp16(kdst + row * 272 + ch * 16, ks + row * 128 + ch * 8);
        }
        unsigned vdst = sb + ATT_V + slot * 18432;
        const __half* vs = Vtg + kt * 64;
        for (int lin = tid; lin < 1024; lin += 384) {
            int row = lin >> 3, ch = lin & 7;
            cp16(vdst + row * 144 + ch * 16, vs + (size_t)row * NT + ch * 8);
        }
    };

    // prologue: Q (group 0), KV0 (group 1), KV1 (group 2)
    for (int lin = tid; lin < 3072; lin += 384) {
        int row = lin >> 4, ch = lin & 15;
        cp16(sb + ATT_QS + row * 272 + ch * 16, Qg + row * 128 + ch * 8);
    }
    CP_COMMIT();
    load_KV(0, 0); CP_COMMIT();
    load_KV(1, 1); CP_COMMIT();

    float O[16][4];
    #pragma unroll
    for (int ni = 0; ni < 16; ni++)
        #pragma unroll
        for (int c = 0; c < 4; c++) O[ni][c] = 0.f;
    float m0 = -1e30f, m1 = -1e30f, l0 = 0.f, l1 = 0.f;

    const unsigned qa = sb + ATT_QS + (q0 + (lane & 15)) * 272 + (lane >> 4) * 16;
    const unsigned kb = (lane & 15) * 272 + (lane >> 4) * 16;
    const unsigned pa = sb + ATT_PS + (q0 + (lane & 15)) * 144 + (lane >> 4) * 16;
    const unsigned vb = (lane & 15) * 144 + (lane >> 4) * 16;

    for (int kt = 0; kt < NKT; kt++) {
        const int slot = kt % 3;
        CP_WAIT1();            // all except newest group done -> Q, KV(kt) ready
        __syncthreads();       // also: slot (kt+2)%3 readers (iter kt-1) done
        if (kt + 2 < NKT) load_KV(kt + 2, (kt + 2) % 3);
        CP_COMMIT();

        // ---- S = Q @ K^T ----
        const unsigned kbase = sb + ATT_K + slot * 17408 + kb;
        float s[8][4];
        #pragma unroll
        for (int ni = 0; ni < 8; ni++)
            #pragma unroll
            for (int c = 0; c < 4; c++) s[ni][c] = 0.f;

        #pragma unroll
        for (int kp = 0; kp < 8; kp++) {
            unsigned a[4];
            ldsm4(a, qa + kp * 32);
            #pragma unroll
            for (int nb = 0; nb < 4; nb++) {
                unsigned bf[4];
                ldsm4(bf, kbase + nb * 16 * 272 + kp * 32);
                mma16(s[2 * nb],     a, bf[0], bf[2]);
                mma16(s[2 * nb + 1], a, bf[1], bf[3]);
            }
        }

        // ---- online softmax (rows are warp-private) ----
        float mx0 = -1e30f, mx1 = -1e30f;
        #pragma unroll
        for (int ni = 0; ni < 8; ni++) {
            mx0 = fmaxf(mx0, fmaxf(s[ni][0], s[ni][1]));
            mx1 = fmaxf(mx1, fmaxf(s[ni][2], s[ni][3]));
        }
        mx0 = fmaxf(mx0, __shfl_xor_sync(0xffffffffu, mx0, 1));
        mx0 = fmaxf(mx0, __shfl_xor_sync(0xffffffffu, mx0, 2));
        mx1 = fmaxf(mx1, __shfl_xor_sync(0xffffffffu, mx1, 1));
        mx1 = fmaxf(mx1, __shfl_xor_sync(0xffffffffu, mx1, 2));

        float mn0 = fmaxf(m0, mx0), mn1 = fmaxf(m1, mx1);
        float al0 = fexp(m0 - mn0), al1 = fexp(m1 - mn1);
        float ls0 = 0.f, ls1 = 0.f;
        #pragma unroll
        for (int ni = 0; ni < 8; ni++) {
            float p0 = fexp(s[ni][0] - mn0);
            float p1 = fexp(s[ni][1] - mn0);
            float p2 = fexp(s[ni][2] - mn1);
            float p3 = fexp(s[ni][3] - mn1);
            ls0 += p0 + p1; ls1 += p2 + p3;
            int cb = (ni * 8 + lm * 2) * 2;
            *(__half2*)(smem + ATT_PS + (q0 + l4) * 144 + cb) =
                __floats2half2_rn(p0, p1);
            *(__half2*)(smem + ATT_PS + (q0 + l4 + 8) * 144 + cb) =
                __floats2half2_rn(p2, p3);
        }
        ls0 += __shfl_xor_sync(0xffffffffu, ls0, 1);
        ls0 += __shfl_xor_sync(0xffffffffu, ls0, 2);
        ls1 += __shfl_xor_sync(0xffffffffu, ls1, 1);
        ls1 += __shfl_xor_sync(0xffffffffu, ls1, 2);
        l0 = l0 * al0 + ls0;  m0 = mn0;
        l1 = l1 * al1 + ls1;  m1 = mn1;
        #pragma unroll
        for (int ni = 0; ni < 16; ni++) {
            O[ni][0] *= al0; O[ni][1] *= al0;
            O[ni][2] *= al1; O[ni][3] *= al1;
        }
        __syncwarp();          // P stores visible to this warp's ldsm

        // ---- O += P @ V ----
        const unsigned vbase = sb + ATT_V + slot * 18432 + vb;
        #pragma unroll
        for (int kp = 0; kp < 4; kp++) {
            unsigned a[4];
            ldsm4(a, pa + kp * 32);
            #pragma unroll
            for (int g = 0; g < 8; g++) {
                unsigned bf[4];
                ldsm4(bf, vbase + g * 16 * 144 + kp * 32);
                mma16(O[2 * g],     a, bf[0], bf[2]);
                mma16(O[2 * g + 1], a, bf[1], bf[3]);
            }
        }
        // no trailing barrier: next iteration's syncthreads protects reuse
    }

    // epilogue
    float inv0 = 1.0f / l0, inv1 = 1.0f / l1;
    size_t r0 = (size_t)qt * 192 + q0 + l4;
    __half* op0 = g_o + ((size_t)b * NT + r0) * DIM + h * HD;
    __half* op1 = g_o + ((size_t)b * NT + r0 + 8) * DIM + h * HD;
    #pragma unroll
    for (int ni = 0; ni < 16; ni++) {
        int cc = ni * 8 + lm * 2;
        *(__half2*)(op0 + cc) = __floats2half2_rn(O[ni][0] * inv0,
                                                  O[ni][1] * inv0);
        *(__half2*)(op1 + cc) = __floats2half2_rn(O[ni][2] * inv1,
                                                  O[ni][3] * inv1);
    }
}

// ------------------------- launch --------------------------------------------
extern "C" void kernel_launch(void* const* d_in, const int* in_sizes, int n_in,
                              void* d_out, int out_size)
{
    (void)in_sizes; (void)n_in; (void)out_size;

    const float* input     = (const float*)d_in[0];
    const float* context   = (const float*)d_in[1];
    const float* W_qkv_in  = (const float*)d_in[2];
    const float* b_qkv_in  = (const float*)d_in[3];
    const float* W_qkv_ctx = (const float*)d_in[4];
    const float* b_qkv_ctx = (const float*)d_in[5];
    const float* qs_in     = (const float*)d_in[6];
    const float* ks_in     = (const float*)d_in[7];
    const float* qs_ctx    = (const float*)d_in[8];
    const float* ks_ctx    = (const float*)d_in[9];
    const float* W_out_in  = (const float*)d_in[10];
    const float* b_out_in  = (const float*)d_in[11];
    const float* W_out_ctx = (const float*)d_in[12];
    const float* b_out_ctx = (const float*)d_in[13];
    float* out = (float*)d_out;

    __half *in_r, *ctx_r;
    cudaGetSymbolAddress((void**)&in_r,  g_in_r);
    cudaGetSymbolAddress((void**)&ctx_r, g_ctx_r);

    cudaFuncSetAttribute(qkv_gemm,
                         cudaFuncAttributeMaxDynamicSharedMemorySize, SM_GEMM);
    cudaFuncSetAttribute(out_gemm,
                         cudaFuncAttributeMaxDynamicSharedMemorySize, SM_GEMM);
    cudaFuncSetAttribute(attn_kernel,
                         cudaFuncAttributeMaxDynamicSharedMemorySize, SM_ATTN);

    // 0) prep: A-operand half conversion + weight transpose/convert
    {
        int n40 = BB * S_IN  * DIM / 4;
        int n41 = BB * S_CTX * DIM / 4;
        half_copy2<<<dim3((n40 + 255) / 256, 1, 2), 256>>>(
            input, in_r, n40, context, ctx_r, n41);
    }
    transpose_half4<<<dim3(Q3 / 32, DIM / 32, 4), dim3(32, 8)>>>(
        W_qkv_in, W_qkv_ctx, W_out_in, W_out_ctx);

    // 1) QKV projections (merged)
    qkv_gemm<<<dim3(Q3 / 256, 36), 256, SM_GEMM>>>(b_qkv_in, b_qkv_ctx);

    // 2) RMSNorm + RoPE + scatter
    normrope_kernel<<<dim3(NT, BB), 256>>>(qs_in, ks_in, qs_ctx, ks_ctx);

    // 3) Attention
    attn_kernel<<<dim3(NT / 192, NH, BB), 384, SM_ATTN>>>();

    // 4) Output projections (merged)
    out_gemm<<<dim3(DIM / 256, 36), 256, SM_GEMM>>>(b_out_in, b_out_ctx, out);
}

// round 9
// speedup vs baseline: 5.8454x; 1.0479x over previous
#include <cuda_runtime.h>
#include <cuda_fp16.h>
#include <math.h>
#include <stdint.h>

#define NH    12
#define HD    128
#define DIM   1536
#define BB    2
#define S_IN  2048
#define S_CTX 256
#define NT    (S_IN + S_CTX)   // 2304
#define Q3    (3 * DIM)        // 4608
#define NKT   (NT / 64)        // 36

// ------------------------- scratch (no cudaMalloc allowed) -------------------
static __device__ __half g_qkv_in [(size_t)BB * S_IN  * Q3];
static __device__ __half g_qkv_ctx[(size_t)BB * S_CTX * Q3];
static __device__ __half g_q[(size_t)BB * NH * NT * HD];   // scaled, [b][h][n][d]
static __device__ __half g_k[(size_t)BB * NH * NT * HD];   // [b][h][n][d]
static __device__ __half g_v[(size_t)BB * NH * NT * HD];   // [b][h][n][d]
static __device__ __half g_o[(size_t)BB * NT * DIM];
static __device__ __half g_wt[18874368];                   // transposed weights
static __device__ __half g_in_r [(size_t)BB * S_IN  * DIM];
static __device__ __half g_ctx_r[(size_t)BB * S_CTX * DIM];
static __device__ float2 g_rope[(size_t)NT * 64];          // (cos, sin)

#define WT_QKV_IN  0
#define WT_QKV_CTX 7077888
#define WT_OUT_IN  14155776
#define WT_OUT_CTX 16515072

// ------------------------- helpers -------------------------------------------
__device__ __forceinline__ unsigned smem_u32(const void* p) {
    unsigned a;
    asm("{ .reg .u64 t; cvta.to.shared.u64 t, %1; cvt.u32.u64 %0, t; }"
        : "=r"(a) : "l"(p));
    return a;
}

__device__ __forceinline__ void cp16(unsigned s, const void* g) {
    unsigned long long ga;
    asm("cvta.to.global.u64 %0, %1;" : "=l"(ga) : "l"(g));
    asm volatile("cp.async.cg.shared.global [%0], [%1], 16;"
                 :: "r"(s), "l"(ga));
}
#define CP_COMMIT() asm volatile("cp.async.commit_group;" ::: "memory")
#define CP_WAIT0()  asm volatile("cp.async.wait_group 0;" ::: "memory")
#define CP_WAIT1()  asm volatile("cp.async.wait_group 1;" ::: "memory")
#define CP_WAIT2()  asm volatile("cp.async.wait_group 2;" ::: "memory")

__device__ __forceinline__ void ldsm4(unsigned* r, unsigned addr) {
    asm volatile("ldmatrix.sync.aligned.m8n8.x4.shared.b16 {%0,%1,%2,%3}, [%4];"
        : "=r"(r[0]), "=r"(r[1]), "=r"(r[2]), "=r"(r[3]) : "r"(addr));
}

__device__ __forceinline__ void ldsm4t(unsigned* r, unsigned addr) {
    asm volatile("ldmatrix.sync.aligned.m8n8.x4.trans.shared.b16 {%0,%1,%2,%3}, [%4];"
        : "=r"(r[0]), "=r"(r[1]), "=r"(r[2]), "=r"(r[3]) : "r"(addr));
}

__device__ __forceinline__ void mma16(float* c, const unsigned* a,
                                      unsigned b0, unsigned b1) {
    asm volatile(
        "mma.sync.aligned.m16n8k16.row.col.f32.f16.f16.f32 "
        "{%0,%1,%2,%3}, {%4,%5,%6,%7}, {%8,%9}, {%0,%1,%2,%3};"
        : "+f"(c[0]), "+f"(c[1]), "+f"(c[2]), "+f"(c[3])
        : "r"(a[0]), "r"(a[1]), "r"(a[2]), "r"(a[3]), "r"(b0), "r"(b1));
}

__device__ __forceinline__ float fexp(float x) {
    float r;
    asm("ex2.approx.ftz.f32 %0, %1;" : "=f"(r) : "f"(x * 1.4426950408889634f));
    return r;
}

// ------------------------- one-shot RoPE table -------------------------------
__global__ void __launch_bounds__(64)
rope_table(void)
{
    int pos = blockIdx.x;
    int t   = threadIdx.x;
    double ang = (double)pos * pow(10000.0, -(double)t / 64.0);
    g_rope[(size_t)pos * 64 + t] = make_float2((float)cos(ang), (float)sin(ang));
}

// ------------------------- merged prep kernels -------------------------------
__global__ void __launch_bounds__(256)
half_copy2(const float* __restrict__ in0, __half* __restrict__ out0, int n40,
           const float* __restrict__ in1, __half* __restrict__ out1, int n41)
{
    const float* in = blockIdx.z ? in1 : in0;
    __half* out     = blockIdx.z ? out1 : out0;
    int n4          = blockIdx.z ? n41 : n40;
    int i = blockIdx.x * 256 + threadIdx.x;
    if (i < n4) {
        float4 v = ((const float4*)in)[i];
        ((__half2*)out)[2 * i]     = __floats2half2_rn(v.x, v.y);
        ((__half2*)out)[2 * i + 1] = __floats2half2_rn(v.z, v.w);
    }
}

// W [K=DIM][N] rm -> Wt [N][K] rm (half). z selects which weight.
__global__ void __launch_bounds__(256)
transpose_half4(const float* __restrict__ W0, const float* __restrict__ W1,
                const float* __restrict__ W2, const float* __restrict__ W3)
{
    const float* W; size_t off; int N;
    switch (blockIdx.z) {
        case 0:  W = W0; off = WT_QKV_IN;  N = Q3;  break;
        case 1:  W = W1; off = WT_QKV_CTX; N = Q3;  break;
        case 2:  W = W2; off = WT_OUT_IN;  N = DIM; break;
        default: W = W3; off = WT_OUT_CTX; N = DIM; break;
    }
    if ((int)blockIdx.x * 32 >= N) return;
    __half* Wt = g_wt + off;
    __shared__ float t[32][33];
    int x  = blockIdx.x * 32 + threadIdx.x;   // n
    int y0 = blockIdx.y * 32 + threadIdx.y;   // k
    #pragma unroll
    for (int j = 0; j < 4; j++)
        t[threadIdx.y + j * 8][threadIdx.x] = W[(size_t)(y0 + j * 8) * N + x];
    __syncthreads();
    int x2 = blockIdx.y * 32 + threadIdx.x;   // k
    int y2 = blockIdx.x * 32 + threadIdx.y;   // n
    #pragma unroll
    for (int j = 0; j < 4; j++)
        Wt[(size_t)(y2 + j * 8) * DIM + x2] =
            __float2half_rn(t[threadIdx.x][threadIdx.y + j * 8]);
}

// ------------------------- F16 GEMM core -------------------------------------
#define G_STAGE 30720
#define SM_GEMM (4 * G_STAGE)

__device__ __forceinline__ void gstore(__half* p, float x, float y) {
    *(__half2*)p = __floats2half2_rn(x, y);
}
__device__ __forceinline__ void gstore(float* p, float x, float y) {
    *(float2*)p = make_float2(x, y);
}

template <typename OutT>
__device__ __forceinline__ void gemm_core(
    const __half* __restrict__ Ap, const __half* __restrict__ Wp,
    const float* __restrict__ bp, OutT* __restrict__ Cp,
    int K, int N, char* smem)
{
    const unsigned sb = smem_u32(smem);
    const int tid  = threadIdx.x;
    const int lane = tid & 31;
    const int wid  = tid >> 5;
    const int wm   = (wid & 1) * 64;
    const int wn   = (wid >> 1) * 64;
    const int l4   = lane >> 2;
    const int lm   = lane & 3;
    const int NCH  = K / 32;

    const int lrow = tid >> 1;
    const int lcb  = (tid & 1) * 32;
    auto issue = [&](int c, int st) {
        unsigned as = sb + st * G_STAGE;
        unsigned bs = as + 10240;
        const __half* ag = Ap + (size_t)lrow * K + c * 32 + lcb / 2;
        cp16(as + lrow * 80 + lcb, ag);
        cp16(as + lrow * 80 + lcb + 16, ag + 8);
        #pragma unroll
        for (int j = 0; j < 2; j++) {
            int r = lrow + j * 128;
            const __half* bg = Wp + (size_t)r * K + c * 32 + lcb / 2;
            cp16(bs + r * 80 + lcb, bg);
            cp16(bs + r * 80 + lcb + 16, bg + 8);
        }
    };

    float acc[4][8][4];
    #pragma unroll
    for (int mi = 0; mi < 4; mi++)
        #pragma unroll
        for (int ni = 0; ni < 8; ni++)
            #pragma unroll
            for (int c = 0; c < 4; c++) acc[mi][ni][c] = 0.f;

    issue(0, 0); CP_COMMIT();
    issue(1, 1); CP_COMMIT();
    issue(2, 2); CP_COMMIT();

    const unsigned a_off = (wm + (lane & 15)) * 80 + (lane >> 4) * 16;
    const unsigned b_off = 10240 + (wn + (lane & 15)) * 80 + (lane >> 4) * 16;

    for (int i = 0; i < NCH; i++) {
        CP_WAIT2();
        __syncthreads();
        if (i + 3 < NCH) issue(i + 3, (i + 3) & 3);
        CP_COMMIT();

        unsigned st = sb + (i & 3) * G_STAGE;
        #pragma unroll
        for (int kp = 0; kp < 2; kp++) {
            unsigned af[4][4];
            #pragma unroll
            for (int mi = 0; mi < 4; mi++)
                ldsm4(af[mi], st + a_off + mi * 16 * 80 + kp * 32);
            #pragma unroll
            for (int nb = 0; nb < 4; nb++) {
                unsigned bf[4];
                ldsm4(bf, st + b_off + nb * 16 * 80 + kp * 32);
                #pragma unroll
                for (int mi = 0; mi < 4; mi++) {
                    mma16(acc[mi][2 * nb],     af[mi], bf[0], bf[2]);
                    mma16(acc[mi][2 * nb + 1], af[mi], bf[1], bf[3]);
                }
            }
        }
    }

    #pragma unroll
    for (int mi = 0; mi < 4; mi++) {
        #pragma unroll
        for (int ni = 0; ni < 8; ni++) {
            int r0 = wm + 16 * mi + l4;
            int c0 = wn + 8 * ni + 2 * lm;
            float bx = bp[c0], by = bp[c0 + 1];
            gstore(Cp + (size_t)r0 * N + c0,
                   acc[mi][ni][0] + bx, acc[mi][ni][1] + by);
            gstore(Cp + (size_t)(r0 + 8) * N + c0,
                   acc[mi][ni][2] + bx, acc[mi][ni][3] + by);
        }
    }
}

// merged QKV projections: y<32 -> input rows, y>=32 -> ctx rows
__global__ void __launch_bounds__(256, 1)
qkv_gemm(const float* __restrict__ b_in, const float* __restrict__ b_ctx)
{
    extern __shared__ char smem[];
    int y = blockIdx.y;
    const __half* A; const __half* W; const float* bias; __half* C;
    if (y < 32) {
        A = g_in_r + (size_t)y * 128 * DIM;
        W = g_wt + WT_QKV_IN;  bias = b_in;
        C = g_qkv_in + (size_t)y * 128 * Q3;
    } else {
        int y2 = y - 32;
        A = g_ctx_r + (size_t)y2 * 128 * DIM;
        W = g_wt + WT_QKV_CTX; bias = b_ctx;
        C = g_qkv_ctx + (size_t)y2 * 128 * Q3;
    }
    gemm_core<__half>(A, W + (size_t)blockIdx.x * 256 * DIM,
                      bias + blockIdx.x * 256, C + blockIdx.x * 256,
                      DIM, Q3, smem);
}

// merged output projections: y<32 -> input part (b = y>>4), else ctx part
__global__ void __launch_bounds__(256, 1)
out_gemm(const float* __restrict__ b_in, const float* __restrict__ b_ctx,
         float* __restrict__ out)
{
    extern __shared__ char smem[];
    int y = blockIdx.y;
    const __half* A; const __half* W; const float* bias; float* C;
    if (y < 32) {
        int b = y >> 4, yy = y & 15;
        A = g_o + ((size_t)b * NT + S_CTX + yy * 128) * DIM;
        W = g_wt + WT_OUT_IN;  bias = b_in;
        C = out + ((size_t)b * S_IN + yy * 128) * DIM;
    } else {
        int z = y - 32, b = z >> 1, yy = z & 1;
        A = g_o + ((size_t)b * NT + yy * 128) * DIM;
        W = g_wt + WT_OUT_CTX; bias = b_ctx;
        C = out + (size_t)BB * S_IN * DIM + ((size_t)b * S_CTX + yy * 128) * DIM;
    }
    gemm_core<float>(A, W + (size_t)blockIdx.x * 256 * DIM,
                     bias + blockIdx.x * 256, C + blockIdx.x * 256,
                     DIM, DIM, smem);
}

// ----------------- RMSNorm + RoPE + scatter (half -> half) -------------------
__global__ void __launch_bounds__(256)
normrope_kernel(const float* __restrict__ qs_in, const float* __restrict__ ks_in,
                const float* __restrict__ qs_ctx, const float* __restrict__ ks_ctx)
{
    const int pos = blockIdx.x;
    const int b   = blockIdx.y;
    const int t   = threadIdx.x;

    __shared__ float buf[DIM];
    __shared__ float red[8];
    __shared__ float cosv[64], sinv[64];

    const __half* src; const float* qs; const float* ks;
    if (pos < S_CTX) {
        src = g_qkv_ctx + ((size_t)b * S_CTX + pos) * Q3;
        qs = qs_ctx; ks = ks_ctx;
    } else {
        src = g_qkv_in + ((size_t)b * S_IN + (pos - S_CTX)) * Q3;
        qs = qs_in; ks = ks_in;
    }

    if (t < 64) {
        float2 cs = g_rope[(size_t)pos * 64 + t];
        cosv[t] = cs.x;
        sinv[t] = cs.y;
    }

    const float qscale = 0.088388347648318447f;   // 128^-0.5

    #pragma unroll
    for (int which = 0; which < 2; which++) {
        const __half* x  = src + which * DIM;
        const float*  sc = which ? ks : qs;
        float v[6];
        float local = 0.f;
        #pragma unroll
        for (int i = 0; i < 6; i++) {
            v[i] = __half2float(x[t + i * 256]);
            local = fmaf(v[i], v[i], local);
        }
        #pragma unroll
        for (int off = 16; off; off >>= 1)
            local += __shfl_xor_sync(0xffffffffu, local, off);
        if ((t & 31) == 0) red[t >> 5] = local;
        __syncthreads();
        float tot = red[0] + red[1] + red[2] + red[3]
                  + red[4] + red[5] + red[6] + red[7];
        float r = rsqrtf(tot * (1.0f / DIM) + 1e-6f);
        #pragma unroll
        for (int i = 0; i < 6; i++)
            buf[t + i * 256] = v[i] * r * sc[t + i * 256];
        __syncthreads();

        __half* dst = which ? g_k : g_q;
        float post = which ? 1.0f : qscale;
        #pragma unroll
        for (int i = 0; i < 6; i++) {
            int e = t + i * 256;
            int hh = e >> 7, d = e & 127, j = d & 63;
            float c = cosv[j], sn = sinv[j];
            float y = (d < 64) ? (buf[e] * c - buf[e + 64] * sn)
                               : (buf[e] * c + buf[e - 64] * sn);
            dst[(((size_t)b * NH + hh) * NT + pos) * HD + d] =
                __float2half_rn(y * post);
        }
        __syncthreads();
    }

    // V: copy to [b][h][n][d] (coalesced 256B chunks per head)
    #pragma unroll
    for (int i = 0; i < 6; i++) {
        int e = t + i * 256;
        int hh = e >> 7, d = e & 127;
        g_v[(((size_t)b * NH + hh) * NT + pos) * HD + d] = src[2 * DIM + e];
    }
}

// ------------------------- F16 flash attention -------------------------------
// 192-query tile, 384 thr / 12 warps. K+V triple-buffered together (one commit
// group per ktile) -> ONE __syncthreads + one wait per ktile. P warp-private.
// V stored [n][d]; PV B-fragments via ldmatrix.trans.
// Smem: Qs 192x272 | K 3x(64x272) | V 3x(64x272) | Ps 192x144
#define ATT_QS   0
#define ATT_K    52224
#define ATT_V    104448
#define ATT_PS   156672
#define SM_ATTN  184320

__global__ void __launch_bounds__(384, 1)
attn_kernel(void)
{
    extern __shared__ char smem[];
    const unsigned sb = smem_u32(smem);

    const int qt = blockIdx.x, h = blockIdx.y, b = blockIdx.z;
    const size_t base = (((size_t)b * NH + h) * NT) * HD;
    const __half* Qg = g_q + base + (size_t)qt * 192 * HD;
    const __half* Kg = g_k + base;
    const __half* Vg = g_v + base;

    const int tid  = threadIdx.x;
    const int lane = tid & 31;
    const int wid  = tid >> 5;        // 0..11
    const int l4   = lane >> 2;
    const int lm   = lane & 3;
    const int q0   = wid * 16;

    auto load_KV = [&](int kt, int slot) {
        unsigned kdst = sb + ATT_K + slot * 17408;
        unsigned vdst = sb + ATT_V + slot * 17408;
        const __half* ks = Kg + (size_t)kt * 64 * HD;
        const __half* vs = Vg + (size_t)kt * 64 * HD;
        for (int lin = tid; lin < 1024; lin += 384) {
            int row = lin >> 4, ch = lin & 15;
            cp16(kdst + row * 272 + ch * 16, ks + row * 128 + ch * 8);
            cp16(vdst + row * 272 + ch * 16, vs + row * 128 + ch * 8);
        }
    };

    // prologue: Q (group 0), KV0 (group 1), KV1 (group 2)
    for (int lin = tid; lin < 3072; lin += 384) {
        int row = lin >> 4, ch = lin & 15;
        cp16(sb + ATT_QS + row * 272 + ch * 16, Qg + row * 128 + ch * 8);
    }
    CP_COMMIT();
    load_KV(0, 0); CP_COMMIT();
    load_KV(1, 1); CP_COMMIT();

    float O[16][4];
    #pragma unroll
    for (int ni = 0; ni < 16; ni++)
        #pragma unroll
        for (int c = 0; c < 4; c++) O[ni][c] = 0.f;
    float m0 = -1e30f, m1 = -1e30f, l0 = 0.f, l1 = 0.f;

    const unsigned qa = sb + ATT_QS + (q0 + (lane & 15)) * 272 + (lane >> 4) * 16;
    const unsigned kb = (lane & 15) * 272 + (lane >> 4) * 16;
    const unsigned pa = sb + ATT_PS + (q0 + (lane & 15)) * 144 + (lane >> 4) * 16;
    // trans-V lane base: matrices (k0-7,d0-7),(k0-7,d8-15),(k8-15,d0-7),(k8-15,d8-15)
    const unsigned vtb = ((lane & 7) + ((lane >> 4) << 3)) * 272
                       + ((lane >> 3) & 1) * 16;

    for (int kt = 0; kt < NKT; kt++) {
        const int slot = kt % 3;
        CP_WAIT1();            // all except newest group done -> Q, KV(kt) ready
        __syncthreads();       // slot (kt+2)%3 readers (iter kt-1) done
        if (kt + 2 < NKT) load_KV(kt + 2, (kt + 2) % 3);
        CP_COMMIT();

        // ---- S = Q @ K^T ----
        const unsigned kbase = sb + ATT_K + slot * 17408 + kb;
        float s[8][4];
        #pragma unroll
        for (int ni = 0; ni < 8; ni++)
            #pragma unroll
            for (int c = 0; c < 4; c++) s[ni][c] = 0.f;

        #pragma unroll
        for (int kp = 0; kp < 8; kp++) {
            unsigned a[4];
            ldsm4(a, qa + kp * 32);
            #pragma unroll
            for (int nb = 0; nb < 4; nb++) {
                unsigned bf[4];
                ldsm4(bf, kbase + nb * 16 * 272 + kp * 32);
                mma16(s[2 * nb],     a, bf[0], bf[2]);
                mma16(s[2 * nb + 1], a, bf[1], bf[3]);
            }
        }

        // ---- online softmax (rows are warp-private) ----
        float mx0 = -1e30f, mx1 = -1e30f;
        #pragma unroll
        for (int ni = 0; ni < 8; ni++) {
            mx0 = fmaxf(mx0, fmaxf(s[ni][0], s[ni][1]));
            mx1 = fmaxf(mx1, fmaxf(s[ni][2], s[ni][3]));
        }
        mx0 = fmaxf(mx0, __shfl_xor_sync(0xffffffffu, mx0, 1));
        mx0 = fmaxf(mx0, __shfl_xor_sync(0xffffffffu, mx0, 2));
        mx1 = fmaxf(mx1, __shfl_xor_sync(0xffffffffu, mx1, 1));
        mx1 = fmaxf(mx1, __shfl_xor_sync(0xffffffffu, mx1, 2));

        float mn0 = fmaxf(m0, mx0), mn1 = fmaxf(m1, mx1);
        float al0 = fexp(m0 - mn0), al1 = fexp(m1 - mn1);
        float ls0 = 0.f, ls1 = 0.f;
        #pragma unroll
        for (int ni = 0; ni < 8; ni++) {
            float p0 = fexp(s[ni][0] - mn0);
            float p1 = fexp(s[ni][1] - mn0);
            float p2 = fexp(s[ni][2] - mn1);
            float p3 = fexp(s[ni][3] - mn1);
            ls0 += p0 + p1; ls1 += p2 + p3;
            int cb = (ni * 8 + lm * 2) * 2;
            *(__half2*)(smem + ATT_PS + (q0 + l4) * 144 + cb) =
                __floats2half2_rn(p0, p1);
            *(__half2*)(smem + ATT_PS + (q0 + l4 + 8) * 144 + cb) =
                __floats2half2_rn(p2, p3);
        }
        ls0 += __shfl_xor_sync(0xffffffffu, ls0, 1);
        ls0 += __shfl_xor_sync(0xffffffffu, ls0, 2);
        ls1 += __shfl_xor_sync(0xffffffffu, ls1, 1);
        ls1 += __shfl_xor_sync(0xffffffffu, ls1, 2);
        l0 = l0 * al0 + ls0;  m0 = mn0;
        l1 = l1 * al1 + ls1;  m1 = mn1;
        #pragma unroll
        for (int ni = 0; ni < 16; ni++) {
            O[ni][0] *= al0; O[ni][1] *= al0;
            O[ni][2] *= al1; O[ni][3] *= al1;
        }
        __syncwarp();          // P stores visible to this warp's ldsm

        // ---- O += P @ V (V row-major, trans ldmatrix) ----
        const unsigned vbase = sb + ATT_V + slot * 17408 + vtb;
        #pragma unroll
        for (int kp = 0; kp < 4; kp++) {
            unsigned a[4];
            ldsm4(a, pa + kp * 32);
            #pragma unroll
            for (int g = 0; g < 8; g++) {
                unsigned bf[4];
                ldsm4t(bf, vbase + kp * 16 * 272 + g * 32);
                mma16(O[2 * g],     a, bf[0], bf[2]);
                mma16(O[2 * g + 1], a, bf[1], bf[3]);
            }
        }
        // no trailing barrier: next iteration's syncthreads protects reuse
    }

    // epilogue
    float inv0 = 1.0f / l0, inv1 = 1.0f / l1;
    size_t r0 = (size_t)qt * 192 + q0 + l4;
    __half* op0 = g_o + ((size_t)b * NT + r0) * DIM + h * HD;
    __half* op1 = g_o + ((size_t)b * NT + r0 + 8) * DIM + h * HD;
    #pragma unroll
    for (int ni = 0; ni < 16; ni++) {
        int cc = ni * 8 + lm * 2;
        *(__half2*)(op0 + cc) = __floats2half2_rn(O[ni][0] * inv0,
                                                  O[ni][1] * inv0);
        *(__half2*)(op1 + cc) = __floats2half2_rn(O[ni][2] * inv1,
                                                  O[ni][3] * inv1);
    }
}

// ------------------------- launch --------------------------------------------
extern "C" void kernel_launch(void* const* d_in, const int* in_sizes, int n_in,
                              void* d_out, int out_size)
{
    (void)in_sizes; (void)n_in; (void)out_size;

    const float* input     = (const float*)d_in[0];
    const float* context   = (const float*)d_in[1];
    const float* W_qkv_in  = (const float*)d_in[2];
    const float* b_qkv_in  = (const float*)d_in[3];
    const float* W_qkv_ctx = (const float*)d_in[4];
    const float* b_qkv_ctx = (const float*)d_in[5];
    const float* qs_in     = (const float*)d_in[6];
    const float* ks_in     = (const float*)d_in[7];
    const float* qs_ctx    = (const float*)d_in[8];
    const float* ks_ctx    = (const float*)d_in[9];
    const float* W_out_in  = (const float*)d_in[10];
    const float* b_out_in  = (const float*)d_in[11];
    const float* W_out_ctx = (const float*)d_in[12];
    const float* b_out_ctx = (const float*)d_in[13];
    float* out = (float*)d_out;

    __half *in_r, *ctx_r;
    cudaGetSymbolAddress((void**)&in_r,  g_in_r);
    cudaGetSymbolAddress((void**)&ctx_r, g_ctx_r);

    cudaFuncSetAttribute(qkv_gemm,
                         cudaFuncAttributeMaxDynamicSharedMemorySize, SM_GEMM);
    cudaFuncSetAttribute(out_gemm,
                         cudaFuncAttributeMaxDynamicSharedMemorySize, SM_GEMM);
    cudaFuncSetAttribute(attn_kernel,
                         cudaFuncAttributeMaxDynamicSharedMemorySize, SM_ATTN);

    // 0) prep: conversions, weight transpose, rope table
    {
        int n40 = BB * S_IN  * DIM / 4;
        int n41 = BB * S_CTX * DIM / 4;
        half_copy2<<<dim3((n40 + 255) / 256, 1, 2), 256>>>(
            input, in_r, n40, context, ctx_r, n41);
    }
    transpose_half4<<<dim3(Q3 / 32, DIM / 32, 4), dim3(32, 8)>>>(
        W_qkv_in, W_qkv_ctx, W_out_in, W_out_ctx);
    rope_table<<<NT, 64>>>();

    // 1) QKV projections (merged)
    qkv_gemm<<<dim3(Q3 / 256, 36), 256, SM_GEMM>>>(b_qkv_in, b_qkv_ctx);

    // 2) RMSNorm + RoPE + scatter
    normrope_kernel<<<dim3(NT, BB), 256>>>(qs_in, ks_in, qs_ctx, ks_ctx);

    // 3) Attention
    attn_kernel<<<dim3(NT / 192, NH, BB), 384, SM_ATTN>>>();

    // 4) Output projections (merged)
    out_gemm<<<dim3(DIM / 256, 36), 256, SM_GEMM>>>(b_out_in, b_out_ctx, out);
}

// round 10
// speedup vs baseline: 6.5684x; 1.1237x over previous
#include <cuda_runtime.h>
#include <cuda_fp16.h>
#include <math.h>
#include <stdint.h>

#define NH    12
#define HD    128
#define DIM   1536
#define BB    2
#define S_IN  2048
#define S_CTX 256
#define NT    (S_IN + S_CTX)   // 2304
#define Q3    (3 * DIM)        // 4608
#define NKT   (NT / 64)        // 36

// ------------------------- scratch (no cudaMalloc allowed) -------------------
static __device__ __half g_qkv_in [(size_t)BB * S_IN  * Q3];
static __device__ __half g_qkv_ctx[(size_t)BB * S_CTX * Q3];
static __device__ __half g_q[(size_t)BB * NH * NT * HD];   // scaled, [b][h][n][d]
static __device__ __half g_k[(size_t)BB * NH * NT * HD];   // [b][h][n][d]
static __device__ __half g_v[(size_t)BB * NH * NT * HD];   // [b][h][n][d]
static __device__ __half g_o[(size_t)BB * NT * DIM];
static __device__ __half g_wt[18874368];                   // transposed weights
static __device__ __half g_in_r [(size_t)BB * S_IN  * DIM];
static __device__ __half g_ctx_r[(size_t)BB * S_CTX * DIM];
static __device__ float2 g_rope[(size_t)NT * 64];          // (cos, sin)

#define WT_QKV_IN  0
#define WT_QKV_CTX 7077888
#define WT_OUT_IN  14155776
#define WT_OUT_CTX 16515072

// ------------------------- helpers -------------------------------------------
__device__ __forceinline__ unsigned smem_u32(const void* p) {
    unsigned a;
    asm("{ .reg .u64 t; cvta.to.shared.u64 t, %1; cvt.u32.u64 %0, t; }"
        : "=r"(a) : "l"(p));
    return a;
}

__device__ __forceinline__ void cp16(unsigned s, const void* g) {
    unsigned long long ga;
    asm("cvta.to.global.u64 %0, %1;" : "=l"(ga) : "l"(g));
    asm volatile("cp.async.cg.shared.global [%0], [%1], 16;"
                 :: "r"(s), "l"(ga));
}
#define CP_COMMIT() asm volatile("cp.async.commit_group;" ::: "memory")
#define CP_WAIT0()  asm volatile("cp.async.wait_group 0;" ::: "memory")
#define CP_WAIT1()  asm volatile("cp.async.wait_group 1;" ::: "memory")
#define CP_WAIT2()  asm volatile("cp.async.wait_group 2;" ::: "memory")

__device__ __forceinline__ void ldsm4(unsigned* r, unsigned addr) {
    asm volatile("ldmatrix.sync.aligned.m8n8.x4.shared.b16 {%0,%1,%2,%3}, [%4];"
        : "=r"(r[0]), "=r"(r[1]), "=r"(r[2]), "=r"(r[3]) : "r"(addr));
}

__device__ __forceinline__ void ldsm4t(unsigned* r, unsigned addr) {
    asm volatile("ldmatrix.sync.aligned.m8n8.x4.trans.shared.b16 {%0,%1,%2,%3}, [%4];"
        : "=r"(r[0]), "=r"(r[1]), "=r"(r[2]), "=r"(r[3]) : "r"(addr));
}

__device__ __forceinline__ void mma16(float* c, const unsigned* a,
                                      unsigned b0, unsigned b1) {
    asm volatile(
        "mma.sync.aligned.m16n8k16.row.col.f32.f16.f16.f32 "
        "{%0,%1,%2,%3}, {%4,%5,%6,%7}, {%8,%9}, {%0,%1,%2,%3};"
        : "+f"(c[0]), "+f"(c[1]), "+f"(c[2]), "+f"(c[3])
        : "r"(a[0]), "r"(a[1]), "r"(a[2]), "r"(a[3]), "r"(b0), "r"(b1));
}

__device__ __forceinline__ float fexp(float x) {
    float r;
    asm("ex2.approx.ftz.f32 %0, %1;" : "=f"(r) : "f"(x * 1.4426950408889634f));
    return r;
}

// ------------------------- one-shot RoPE table -------------------------------
__global__ void __launch_bounds__(64)
rope_table(void)
{
    int pos = blockIdx.x;
    int t   = threadIdx.x;
    double ang = (double)pos * pow(10000.0, -(double)t / 64.0);
    g_rope[(size_t)pos * 64 + t] = make_float2((float)cos(ang), (float)sin(ang));
}

// ------------------------- merged prep kernels -------------------------------
__global__ void __launch_bounds__(256)
half_copy2(const float* __restrict__ in0, __half* __restrict__ out0, int n40,
           const float* __restrict__ in1, __half* __restrict__ out1, int n41)
{
    const float* in = blockIdx.z ? in1 : in0;
    __half* out     = blockIdx.z ? out1 : out0;
    int n4          = blockIdx.z ? n41 : n40;
    int i = blockIdx.x * 256 + threadIdx.x;
    if (i < n4) {
        float4 v = ((const float4*)in)[i];
        ((__half2*)out)[2 * i]     = __floats2half2_rn(v.x, v.y);
        ((__half2*)out)[2 * i + 1] = __floats2half2_rn(v.z, v.w);
    }
}

// W [K=DIM][N] rm -> Wt [N][K] rm (half). z selects which weight.
__global__ void __launch_bounds__(256)
transpose_half4(const float* __restrict__ W0, const float* __restrict__ W1,
                const float* __restrict__ W2, const float* __restrict__ W3)
{
    const float* W; size_t off; int N;
    switch (blockIdx.z) {
        case 0:  W = W0; off = WT_QKV_IN;  N = Q3;  break;
        case 1:  W = W1; off = WT_QKV_CTX; N = Q3;  break;
        case 2:  W = W2; off = WT_OUT_IN;  N = DIM; break;
        default: W = W3; off = WT_OUT_CTX; N = DIM; break;
    }
    if ((int)blockIdx.x * 32 >= N) return;
    __half* Wt = g_wt + off;
    __shared__ float t[32][33];
    int x  = blockIdx.x * 32 + threadIdx.x;   // n
    int y0 = blockIdx.y * 32 + threadIdx.y;   // k
    #pragma unroll
    for (int j = 0; j < 4; j++)
        t[threadIdx.y + j * 8][threadIdx.x] = W[(size_t)(y0 + j * 8) * N + x];
    __syncthreads();
    int x2 = blockIdx.y * 32 + threadIdx.x;   // k
    int y2 = blockIdx.x * 32 + threadIdx.y;   // n
    #pragma unroll
    for (int j = 0; j < 4; j++)
        Wt[(size_t)(y2 + j * 8) * DIM + x2] =
            __float2half_rn(t[threadIdx.x][threadIdx.y + j * 8]);
}

// ------------------------- F16 GEMM core -------------------------------------
// CTA tile 128x128, warp tile 64x32, k-chunk 32, 4-stage cp.async ring.
// 20.5 KB/stage -> 82 KB total -> 2 CTAs/SM (16 warps) for latency hiding.
#define G_STAGE 20480
#define SM_GEMM (4 * G_STAGE)

__device__ __forceinline__ void gstore(__half* p, float x, float y) {
    *(__half2*)p = __floats2half2_rn(x, y);
}
__device__ __forceinline__ void gstore(float* p, float x, float y) {
    *(float2*)p = make_float2(x, y);
}

template <typename OutT>
__device__ __forceinline__ void gemm_core(
    const __half* __restrict__ Ap, const __half* __restrict__ Wp,
    const float* __restrict__ bp, OutT* __restrict__ Cp,
    int K, int N, char* smem)
{
    const unsigned sb = smem_u32(smem);
    const int tid  = threadIdx.x;
    const int lane = tid & 31;
    const int wid  = tid >> 5;
    const int wm   = (wid & 1) * 64;
    const int wn   = (wid >> 1) * 32;
    const int l4   = lane >> 2;
    const int lm   = lane & 3;
    const int NCH  = K / 32;

    const int lrow = tid >> 1;            // 0..127
    const int lcb  = (tid & 1) * 32;      // byte offset within 64B row
    auto issue = [&](int c, int st) {
        unsigned as = sb + st * G_STAGE;
        unsigned bs = as + 10240;
        const __half* ag = Ap + (size_t)lrow * K + c * 32 + lcb / 2;
        cp16(as + lrow * 80 + lcb, ag);
        cp16(as + lrow * 80 + lcb + 16, ag + 8);
        const __half* bg = Wp + (size_t)lrow * K + c * 32 + lcb / 2;
        cp16(bs + lrow * 80 + lcb, bg);
        cp16(bs + lrow * 80 + lcb + 16, bg + 8);
    };

    float acc[4][4][4];
    #pragma unroll
    for (int mi = 0; mi < 4; mi++)
        #pragma unroll
        for (int ni = 0; ni < 4; ni++)
            #pragma unroll
            for (int c = 0; c < 4; c++) acc[mi][ni][c] = 0.f;

    issue(0, 0); CP_COMMIT();
    issue(1, 1); CP_COMMIT();
    issue(2, 2); CP_COMMIT();

    const unsigned a_off = (wm + (lane & 15)) * 80 + (lane >> 4) * 16;
    const unsigned b_off = 10240 + (wn + (lane & 15)) * 80 + (lane >> 4) * 16;

    for (int i = 0; i < NCH; i++) {
        CP_WAIT2();
        __syncthreads();
        if (i + 3 < NCH) issue(i + 3, (i + 3) & 3);
        CP_COMMIT();

        unsigned st = sb + (i & 3) * G_STAGE;
        #pragma unroll
        for (int kp = 0; kp < 2; kp++) {
            unsigned af[4][4];
            #pragma unroll
            for (int mi = 0; mi < 4; mi++)
                ldsm4(af[mi], st + a_off + mi * 16 * 80 + kp * 32);
            #pragma unroll
            for (int nb = 0; nb < 2; nb++) {
                unsigned bf[4];
                ldsm4(bf, st + b_off + nb * 16 * 80 + kp * 32);
                #pragma unroll
                for (int mi = 0; mi < 4; mi++) {
                    mma16(acc[mi][2 * nb],     af[mi], bf[0], bf[2]);
                    mma16(acc[mi][2 * nb + 1], af[mi], bf[1], bf[3]);
                }
            }
        }
    }

    #pragma unroll
    for (int mi = 0; mi < 4; mi++) {
        #pragma unroll
        for (int ni = 0; ni < 4; ni++) {
            int r0 = wm + 16 * mi + l4;
            int c0 = wn + 8 * ni + 2 * lm;
            float bx = bp[c0], by = bp[c0 + 1];
            gstore(Cp + (size_t)r0 * N + c0,
                   acc[mi][ni][0] + bx, acc[mi][ni][1] + by);
            gstore(Cp + (size_t)(r0 + 8) * N + c0,
                   acc[mi][ni][2] + bx, acc[mi][ni][3] + by);
        }
    }
}

// merged QKV projections: y<32 -> input rows, y>=32 -> ctx rows
__global__ void __launch_bounds__(256, 2)
qkv_gemm(const float* __restrict__ b_in, const float* __restrict__ b_ctx)
{
    extern __shared__ char smem[];
    int y = blockIdx.y;
    const __half* A; const __half* W; const float* bias; __half* C;
    if (y < 32) {
        A = g_in_r + (size_t)y * 128 * DIM;
        W = g_wt + WT_QKV_IN;  bias = b_in;
        C = g_qkv_in + (size_t)y * 128 * Q3;
    } else {
        int y2 = y - 32;
        A = g_ctx_r + (size_t)y2 * 128 * DIM;
        W = g_wt + WT_QKV_CTX; bias = b_ctx;
        C = g_qkv_ctx + (size_t)y2 * 128 * Q3;
    }
    gemm_core<__half>(A, W + (size_t)blockIdx.x * 128 * DIM,
                      bias + blockIdx.x * 128, C + blockIdx.x * 128,
                      DIM, Q3, smem);
}

// merged output projections: y<32 -> input part (b = y>>4), else ctx part
__global__ void __launch_bounds__(256, 2)
out_gemm(const float* __restrict__ b_in, const float* __restrict__ b_ctx,
         float* __restrict__ out)
{
    extern __shared__ char smem[];
    int y = blockIdx.y;
    const __half* A; const __half* W; const float* bias; float* C;
    if (y < 32) {
        int b = y >> 4, yy = y & 15;
        A = g_o + ((size_t)b * NT + S_CTX + yy * 128) * DIM;
        W = g_wt + WT_OUT_IN;  bias = b_in;
        C = out + ((size_t)b * S_IN + yy * 128) * DIM;
    } else {
        int z = y - 32, b = z >> 1, yy = z & 1;
        A = g_o + ((size_t)b * NT + yy * 128) * DIM;
        W = g_wt + WT_OUT_CTX; bias = b_ctx;
        C = out + (size_t)BB * S_IN * DIM + ((size_t)b * S_CTX + yy * 128) * DIM;
    }
    gemm_core<float>(A, W + (size_t)blockIdx.x * 128 * DIM,
                     bias + blockIdx.x * 128, C + blockIdx.x * 128,
                     DIM, DIM, smem);
}

// ----------------- RMSNorm + RoPE + scatter (half -> half) -------------------
__global__ void __launch_bounds__(256)
normrope_kernel(const float* __restrict__ qs_in, const float* __restrict__ ks_in,
                const float* __restrict__ qs_ctx, const float* __restrict__ ks_ctx)
{
    const int pos = blockIdx.x;
    const int b   = blockIdx.y;
    const int t   = threadIdx.x;

    __shared__ float buf[DIM];
    __shared__ float red[8];
    __shared__ float cosv[64], sinv[64];

    const __half* src; const float* qs; const float* ks;
    if (pos < S_CTX) {
        src = g_qkv_ctx + ((size_t)b * S_CTX + pos) * Q3;
        qs = qs_ctx; ks = ks_ctx;
    } else {
        src = g_qkv_in + ((size_t)b * S_IN + (pos - S_CTX)) * Q3;
        qs = qs_in; ks = ks_in;
    }

    if (t < 64) {
        float2 cs = g_rope[(size_t)pos * 64 + t];
        cosv[t] = cs.x;
        sinv[t] = cs.y;
    }

    const float qscale = 0.088388347648318447f;   // 128^-0.5

    #pragma unroll
    for (int which = 0; which < 2; which++) {
        const __half* x  = src + which * DIM;
        const float*  sc = which ? ks : qs;
        float v[6];
        float local = 0.f;
        #pragma unroll
        for (int i = 0; i < 6; i++) {
            v[i] = __half2float(x[t + i * 256]);
            local = fmaf(v[i], v[i], local);
        }
        #pragma unroll
        for (int off = 16; off; off >>= 1)
            local += __shfl_xor_sync(0xffffffffu, local, off);
        if ((t & 31) == 0) red[t >> 5] = local;
        __syncthreads();
        float tot = red[0] + red[1] + red[2] + red[3]
                  + red[4] + red[5] + red[6] + red[7];
        float r = rsqrtf(tot * (1.0f / DIM) + 1e-6f);
        #pragma unroll
        for (int i = 0; i < 6; i++)
            buf[t + i * 256] = v[i] * r * sc[t + i * 256];
        __syncthreads();

        __half* dst = which ? g_k : g_q;
        float post = which ? 1.0f : qscale;
        #pragma unroll
        for (int i = 0; i < 6; i++) {
            int e = t + i * 256;
            int hh = e >> 7, d = e & 127, j = d & 63;
            float c = cosv[j], sn = sinv[j];
            float y = (d < 64) ? (buf[e] * c - buf[e + 64] * sn)
                               : (buf[e] * c + buf[e - 64] * sn);
            dst[(((size_t)b * NH + hh) * NT + pos) * HD + d] =
                __float2half_rn(y * post);
        }
        __syncthreads();
    }

    // V: copy to [b][h][n][d] (coalesced 256B chunks per head)
    #pragma unroll
    for (int i = 0; i < 6; i++) {
        int e = t + i * 256;
        int hh = e >> 7, d = e & 127;
        g_v[(((size_t)b * NH + hh) * NT + pos) * HD + d] = src[2 * DIM + e];
    }
}

// ------------------------- F16 flash attention -------------------------------
// 192-query tile, 384 thr / 12 warps. K+V triple-buffered together (one commit
// group per ktile) -> ONE __syncthreads + one wait per ktile. P warp-private.
// V stored [n][d]; PV B-fragments via ldmatrix.trans.
// Smem: Qs 192x272 | K 3x(64x272) | V 3x(64x272) | Ps 192x144
#define ATT_QS   0
#define ATT_K    52224
#define ATT_V    104448
#define ATT_PS   156672
#define SM_ATTN  184320

__global__ void __launch_bounds__(384, 1)
attn_kernel(void)
{
    extern __shared__ char smem[];
    const unsigned sb = smem_u32(smem);

    const int qt = blockIdx.x, h = blockIdx.y, b = blockIdx.z;
    const size_t base = (((size_t)b * NH + h) * NT) * HD;
    const __half* Qg = g_q + base + (size_t)qt * 192 * HD;
    const __half* Kg = g_k + base;
    const __half* Vg = g_v + base;

    const int tid  = threadIdx.x;
    const int lane = tid & 31;
    const int wid  = tid >> 5;        // 0..11
    const int l4   = lane >> 2;
    const int lm   = lane & 3;
    const int q0   = wid * 16;

    auto load_KV = [&](int kt, int slot) {
        unsigned kdst = sb + ATT_K + slot * 17408;
        unsigned vdst = sb + ATT_V + slot * 17408;
        const __half* ks = Kg + (size_t)kt * 64 * HD;
        const __half* vs = Vg + (size_t)kt * 64 * HD;
        for (int lin = tid; lin < 1024; lin += 384) {
            int row = lin >> 4, ch = lin & 15;
            cp16(kdst + row * 272 + ch * 16, ks + row * 128 + ch * 8);
            cp16(vdst + row * 272 + ch * 16, vs + row * 128 + ch * 8);
        }
    };

    // prologue: Q (group 0), KV0 (group 1), KV1 (group 2)
    for (int lin = tid; lin < 3072; lin += 384) {
        int row = lin >> 4, ch = lin & 15;
        cp16(sb + ATT_QS + row * 272 + ch * 16, Qg + row * 128 + ch * 8);
    }
    CP_COMMIT();
    load_KV(0, 0); CP_COMMIT();
    load_KV(1, 1); CP_COMMIT();

    float O[16][4];
    #pragma unroll
    for (int ni = 0; ni < 16; ni++)
        #pragma unroll
        for (int c = 0; c < 4; c++) O[ni][c] = 0.f;
    float m0 = -1e30f, m1 = -1e30f, l0 = 0.f, l1 = 0.f;

    const unsigned qa = sb + ATT_QS + (q0 + (lane & 15)) * 272 + (lane >> 4) * 16;
    const unsigned kb = (lane & 15) * 272 + (lane >> 4) * 16;
    const unsigned pa = sb + ATT_PS + (q0 + (lane & 15)) * 144 + (lane >> 4) * 16;
    // trans-V lane base: matrices (k0-7,d0-7),(k0-7,d8-15),(k8-15,d0-7),(k8-15,d8-15)
    const unsigned vtb = ((lane & 7) + ((lane >> 4) << 3)) * 272
                       + ((lane >> 3) & 1) * 16;

    for (int kt = 0; kt < NKT; kt++) {
        const int slot = kt % 3;
        CP_WAIT1();            // all except newest group done -> Q, KV(kt) ready
        __syncthreads();       // slot (kt+2)%3 readers (iter kt-1) done
        if (kt + 2 < NKT) load_KV(kt + 2, (kt + 2) % 3);
        CP_COMMIT();

        // ---- S = Q @ K^T ----
        const unsigned kbase = sb + ATT_K + slot * 17408 + kb;
        float s[8][4];
        #pragma unroll
        for (int ni = 0; ni < 8; ni++)
            #pragma unroll
            for (int c = 0; c < 4; c++) s[ni][c] = 0.f;

        #pragma unroll
        for (int kp = 0; kp < 8; kp++) {
            unsigned a[4];
            ldsm4(a, qa + kp * 32);
            #pragma unroll
            for (int nb = 0; nb < 4; nb++) {
                unsigned bf[4];
                ldsm4(bf, kbase + nb * 16 * 272 + kp * 32);
                mma16(s[2 * nb],     a, bf[0], bf[2]);
                mma16(s[2 * nb + 1], a, bf[1], bf[3]);
            }
        }

        // ---- online softmax (rows are warp-private) ----
        float mx0 = -1e30f, mx1 = -1e30f;
        #pragma unroll
        for (int ni = 0; ni < 8; ni++) {
            mx0 = fmaxf(mx0, fmaxf(s[ni][0], s[ni][1]));
            mx1 = fmaxf(mx1, fmaxf(s[ni][2], s[ni][3]));
        }
        mx0 = fmaxf(mx0, __shfl_xor_sync(0xffffffffu, mx0, 1));
        mx0 = fmaxf(mx0, __shfl_xor_sync(0xffffffffu, mx0, 2));
        mx1 = fmaxf(mx1, __shfl_xor_sync(0xffffffffu, mx1, 1));
        mx1 = fmaxf(mx1, __shfl_xor_sync(0xffffffffu, mx1, 2));

        float mn0 = fmaxf(m0, mx0), mn1 = fmaxf(m1, mx1);
        float al0 = fexp(m0 - mn0), al1 = fexp(m1 - mn1);
        float ls0 = 0.f, ls1 = 0.f;
        #pragma unroll
        for (int ni = 0; ni < 8; ni++) {
            float p0 = fexp(s[ni][0] - mn0);
            float p1 = fexp(s[ni][1] - mn0);
            float p2 = fexp(s[ni][2] - mn1);
            float p3 = fexp(s[ni][3] - mn1);
            ls0 += p0 + p1; ls1 += p2 + p3;
            int cb = (ni * 8 + lm * 2) * 2;
            *(__half2*)(smem + ATT_PS + (q0 + l4) * 144 + cb) =
                __floats2half2_rn(p0, p1);
            *(__half2*)(smem + ATT_PS + (q0 + l4 + 8) * 144 + cb) =
                __floats2half2_rn(p2, p3);
        }
        ls0 += __shfl_xor_sync(0xffffffffu, ls0, 1);
        ls0 += __shfl_xor_sync(0xffffffffu, ls0, 2);
        ls1 += __shfl_xor_sync(0xffffffffu, ls1, 1);
        ls1 += __shfl_xor_sync(0xffffffffu, ls1, 2);
        l0 = l0 * al0 + ls0;  m0 = mn0;
        l1 = l1 * al1 + ls1;  m1 = mn1;
        #pragma unroll
        for (int ni = 0; ni < 16; ni++) {
            O[ni][0] *= al0; O[ni][1] *= al0;
            O[ni][2] *= al1; O[ni][3] *= al1;
        }
        __syncwarp();          // P stores visible to this warp's ldsm

        // ---- O += P @ V (V row-major, trans ldmatrix) ----
        const unsigned vbase = sb + ATT_V + slot * 17408 + vtb;
        #pragma unroll
        for (int kp = 0; kp < 4; kp++) {
            unsigned a[4];
            ldsm4(a, pa + kp * 32);
            #pragma unroll
            for (int g = 0; g < 8; g++) {
                unsigned bf[4];
                ldsm4t(bf, vbase + kp * 16 * 272 + g * 32);
                mma16(O[2 * g],     a, bf[0], bf[2]);
                mma16(O[2 * g + 1], a, bf[1], bf[3]);
            }
        }
        // no trailing barrier: next iteration's syncthreads protects reuse
    }

    // epilogue
    float inv0 = 1.0f / l0, inv1 = 1.0f / l1;
    size_t r0 = (size_t)qt * 192 + q0 + l4;
    __half* op0 = g_o + ((size_t)b * NT + r0) * DIM + h * HD;
    __half* op1 = g_o + ((size_t)b * NT + r0 + 8) * DIM + h * HD;
    #pragma unroll
    for (int ni = 0; ni < 16; ni++) {
        int cc = ni * 8 + lm * 2;
        *(__half2*)(op0 + cc) = __floats2half2_rn(O[ni][0] * inv0,
                                                  O[ni][1] * inv0);
        *(__half2*)(op1 + cc) = __floats2half2_rn(O[ni][2] * inv1,
                                                  O[ni][3] * inv1);
    }
}

// ------------------------- launch --------------------------------------------
extern "C" void kernel_launch(void* const* d_in, const int* in_sizes, int n_in,
                              void* d_out, int out_size)
{
    (void)in_sizes; (void)n_in; (void)out_size;

    const float* input     = (const float*)d_in[0];
    const float* context   = (const float*)d_in[1];
    const float* W_qkv_in  = (const float*)d_in[2];
    const float* b_qkv_in  = (const float*)d_in[3];
    const float* W_qkv_ctx = (const float*)d_in[4];
    const float* b_qkv_ctx = (const float*)d_in[5];
    const float* qs_in     = (const float*)d_in[6];
    const float* ks_in     = (const float*)d_in[7];
    const float* qs_ctx    = (const float*)d_in[8];
    const float* ks_ctx    = (const float*)d_in[9];
    const float* W_out_in  = (const float*)d_in[10];
    const float* b_out_in  = (const float*)d_in[11];
    const float* W_out_ctx = (const float*)d_in[12];
    const float* b_out_ctx = (const float*)d_in[13];
    float* out = (float*)d_out;

    __half *in_r, *ctx_r;
    cudaGetSymbolAddress((void**)&in_r,  g_in_r);
    cudaGetSymbolAddress((void**)&ctx_r, g_ctx_r);

    cudaFuncSetAttribute(qkv_gemm,
                         cudaFuncAttributeMaxDynamicSharedMemorySize, SM_GEMM);
    cudaFuncSetAttribute(out_gemm,
                         cudaFuncAttributeMaxDynamicSharedMemorySize, SM_GEMM);
    cudaFuncSetAttribute(attn_kernel,
                         cudaFuncAttributeMaxDynamicSharedMemorySize, SM_ATTN);

    // 0) prep: conversions, weight transpose, rope table
    {
        int n40 = BB * S_IN  * DIM / 4;
        int n41 = BB * S_CTX * DIM / 4;
        half_copy2<<<dim3((n40 + 255) / 256, 1, 2), 256>>>(
            input, in_r, n40, context, ctx_r, n41);
    }
    transpose_half4<<<dim3(Q3 / 32, DIM / 32, 4), dim3(32, 8)>>>(
        W_qkv_in, W_qkv_ctx, W_out_in, W_out_ctx);
    rope_table<<<NT, 64>>>();

    // 1) QKV projections (merged, 128x128 CTA tiles)
    qkv_gemm<<<dim3(Q3 / 128, 36), 256, SM_GEMM>>>(b_qkv_in, b_qkv_ctx);

    // 2) RMSNorm + RoPE + scatter
    normrope_kernel<<<dim3(NT, BB), 256>>>(qs_in, ks_in, qs_ctx, ks_ctx);

    // 3) Attention
    attn_kernel<<<dim3(NT / 192, NH, BB), 384, SM_ATTN>>>();

    // 4) Output projections (merged)
    out_gemm<<<dim3(DIM / 128, 36), 256, SM_GEMM>>>(b_out_in, b_out_ctx, out);
}